// round 4
// baseline (speedup 1.0000x reference)
#include <cuda_runtime.h>
#include <cuda_bf16.h>
#include <cstdint>

// ---------------------------------------------------------------------------
// Arch gate: tcgen05 is sm_103a-ONLY (plain compute_103 phase must compile).
// ---------------------------------------------------------------------------
#if defined(__CUDA_ARCH__) && (__CUDA_ARCH__ == 1030) && defined(__CUDA_ARCH_FEAT_SM103_ALL)
#define TC_OK 1
#else
#define TC_OK 0
#endif

// ---------------------------------------------------------------------------
// Problem constants
// ---------------------------------------------------------------------------
#define N_EXPERTS 30
#define IN_SZ     1024
#define HID       2048
#define BATCH_SZ  8192

// ---------------------------------------------------------------------------
// Device scratch
// ---------------------------------------------------------------------------
__device__ __align__(16) __nv_bfloat16 g_xb [(size_t)BATCH_SZ * IN_SZ];          // 16 MB
__device__ __align__(16) __nv_bfloat16 g_w1b[(size_t)N_EXPERTS * HID * IN_SZ];   // 126 MB, [E][H][K] K-major
__device__ float g_zbuf[(size_t)N_EXPERTS * BATCH_SZ];                            // 1 MB

// ---------------------------------------------------------------------------
// PTX helpers
// ---------------------------------------------------------------------------
__device__ __forceinline__ uint32_t smem_to_u32(const void* p) {
    uint32_t a;
    asm("{ .reg .u64 t; cvta.to.shared.u64 t, %1; cvt.u32.u64 %0, t; }"
        : "=r"(a) : "l"(p));
    return a;
}

__device__ __forceinline__ uint32_t elect_one_pred() {
    uint32_t pred;
    asm volatile(
        "{\n\t.reg .pred p;\n\telect.sync _|p, 0xFFFFFFFF;\n\tselp.b32 %0, 1, 0, p;\n\t}"
        : "=r"(pred));
    return pred;
}

__device__ __forceinline__ uint32_t cluster_rank() {
    uint32_t r;
    asm("mov.u32 %0, %%cluster_ctarank;" : "=r"(r));
    return r;
}

#define MBARRIER_INIT(addr, cnt) \
    asm volatile("mbarrier.init.shared.b64 [%0], %1;" :: "r"((uint32_t)(addr)), "r"((uint32_t)(cnt)) : "memory")

// local wait, acquire at cta scope
#define MBARRIER_WAIT_PARITY(mbar_smem_addr, phase_parity) do { \
    uint32_t _mbar = (uint32_t)(mbar_smem_addr); \
    uint32_t _parity = (uint32_t)(phase_parity); \
    uint32_t _done; \
    asm volatile( \
        "{\n\t.reg .pred p;\n\t" \
        "mbarrier.try_wait.parity.acquire.cta.shared::cta.b64 p, [%1], %2;\n\t" \
        "selp.b32 %0, 1, 0, p;\n\t}" \
        : "=r"(_done) : "r"(_mbar), "r"(_parity) : "memory"); \
    if (!_done) { \
        asm volatile( \
            "{\n\t.reg .pred P1;\n\t" \
            "WAIT_LOOP_%=:\n\t" \
            "mbarrier.try_wait.parity.acquire.cta.shared::cta.b64 P1, [%0], %1, 0x989680;\n\t" \
            "@P1 bra.uni WAIT_DONE_%=;\n\t" \
            "bra.uni WAIT_LOOP_%=;\n\t" \
            "WAIT_DONE_%=:\n\t}" \
            :: "r"(_mbar), "r"(_parity) : "memory"); \
    } \
} while (0)

// cluster-scope acquire wait (leader waiting on peer-produced data)
#define MBARRIER_WAIT_PARITY_CLU(mbar_smem_addr, phase_parity) do { \
    uint32_t _mbar = (uint32_t)(mbar_smem_addr); \
    uint32_t _parity = (uint32_t)(phase_parity); \
    uint32_t _done; \
    asm volatile( \
        "{\n\t.reg .pred p;\n\t" \
        "mbarrier.try_wait.parity.acquire.cluster.shared::cta.b64 p, [%1], %2;\n\t" \
        "selp.b32 %0, 1, 0, p;\n\t}" \
        : "=r"(_done) : "r"(_mbar), "r"(_parity) : "memory"); \
    if (!_done) { \
        asm volatile( \
            "{\n\t.reg .pred P1;\n\t" \
            "WAIT_LOOP_%=:\n\t" \
            "mbarrier.try_wait.parity.acquire.cluster.shared::cta.b64 P1, [%0], %1, 0x989680;\n\t" \
            "@P1 bra.uni WAIT_DONE_%=;\n\t" \
            "bra.uni WAIT_LOOP_%=;\n\t" \
            "WAIT_DONE_%=:\n\t}" \
            :: "r"(_mbar), "r"(_parity) : "memory"); \
    } \
} while (0)

// arrive on the same-offset mbarrier in cluster rank 0
#define MBARRIER_ARRIVE_RANK0(local_mbar_addr) \
    asm volatile( \
        "{\n\t.reg .b32 remAddr32;\n\t" \
        "mapa.shared::cluster.u32 remAddr32, %0, 0;\n\t" \
        "mbarrier.arrive.shared::cluster.b64 _, [remAddr32];\n\t}" \
        :: "r"((uint32_t)(local_mbar_addr)) : "memory")

#define CLUSTER_SYNC() do { \
    asm volatile("barrier.cluster.arrive.aligned;" ::: "memory"); \
    asm volatile("barrier.cluster.wait.aligned;" ::: "memory"); \
} while (0)

#define NAMED_BAR(id, cnt) \
    asm volatile("bar.sync %0, %1;" :: "r"(id), "r"(cnt) : "memory")

__device__ __forceinline__ void cp16(uint32_t dst_smem, const void* src_gmem) {
    asm volatile("cp.async.cg.shared.global [%0], [%1], 16;"
                 :: "r"(dst_smem), "l"(src_gmem) : "memory");
}
__device__ __forceinline__ void cp_commit() { asm volatile("cp.async.commit_group;" ::: "memory"); }
#define CP_WAIT_GROUP(n) asm volatile("cp.async.wait_group %0;" :: "n"(n) : "memory")
#define FENCE_PROXY_ASYNC_SHARED_CTA() asm volatile("fence.proxy.async.shared::cta;" ::: "memory")

#if TC_OK
#define TCGEN05_ALLOC_CG2(smem_result_addr, nCols) \
    asm volatile("tcgen05.alloc.cta_group::2.sync.aligned.shared::cta.b32 [%0], %1;" \
        :: "r"((uint32_t)(smem_result_addr)), "r"((uint32_t)(nCols)) : "memory")

#define TCGEN05_DEALLOC_CG2(tmem_addr, nCols) \
    asm volatile("tcgen05.dealloc.cta_group::2.sync.aligned.b32 %0, %1;" \
        :: "r"(tmem_addr), "r"((uint32_t)(nCols)))

#define TCGEN05_RELINQUISH_CG2() \
    asm volatile("tcgen05.relinquish_alloc_permit.cta_group::2.sync.aligned;")

#define TCGEN05_COMMIT_MC_CG2(mbar_smem_addr, cta_mask) \
    asm volatile("tcgen05.commit.cta_group::2.mbarrier::arrive::one.shared::cluster.multicast::cluster.b64 [%0], %1;" \
        :: "r"((uint32_t)(mbar_smem_addr)), "h"((uint16_t)(cta_mask)) : "memory")

#define TCGEN05_WAIT_LD()  asm volatile("tcgen05.wait::ld.sync.aligned;" ::: "memory")
#define TCGEN05_FENCE_BEFORE() asm volatile("tcgen05.fence::before_thread_sync;" ::: "memory")
#define TCGEN05_FENCE_AFTER()  asm volatile("tcgen05.fence::after_thread_sync;" ::: "memory")

#define TCGEN05_LD_32X32B_X32(r, tmem_addr) \
    asm volatile( \
        "tcgen05.ld.sync.aligned.32x32b.x32.b32 " \
        "{%0, %1, %2, %3, %4, %5, %6, %7, " \
        " %8, %9, %10, %11, %12, %13, %14, %15, " \
        " %16, %17, %18, %19, %20, %21, %22, %23, " \
        " %24, %25, %26, %27, %28, %29, %30, %31}, [%32];" \
        : "=r"((r)[0]),  "=r"((r)[1]),  "=r"((r)[2]),  "=r"((r)[3]), \
          "=r"((r)[4]),  "=r"((r)[5]),  "=r"((r)[6]),  "=r"((r)[7]), \
          "=r"((r)[8]),  "=r"((r)[9]),  "=r"((r)[10]), "=r"((r)[11]), \
          "=r"((r)[12]), "=r"((r)[13]), "=r"((r)[14]), "=r"((r)[15]), \
          "=r"((r)[16]), "=r"((r)[17]), "=r"((r)[18]), "=r"((r)[19]), \
          "=r"((r)[20]), "=r"((r)[21]), "=r"((r)[22]), "=r"((r)[23]), \
          "=r"((r)[24]), "=r"((r)[25]), "=r"((r)[26]), "=r"((r)[27]), \
          "=r"((r)[28]), "=r"((r)[29]), "=r"((r)[30]), "=r"((r)[31]) \
        : "r"(tmem_addr))

// SW128 K-major SMEM descriptor (layout=SW128, Blackwell version=1, LBO=1, SBO=64)
static constexpr uint64_t SMEM_DESC_BASE_SW128 =
    (uint64_t(2) << 61) | (uint64_t(1) << 46) | (uint64_t(64) << 32) | (uint64_t(1) << 16);
#define MAKE_SMEM_DESC(base_addr) \
    (SMEM_DESC_BASE_SW128 | ((uint64_t)((base_addr) >> 4) & 0x3FFF))

// cg2 bf16 SS MMA: D[256,N] += A[256,k16] * B[N,k16]^T (M split 128/128, B split N/2 per CTA)
__device__ __forceinline__ void mma_f16_ss_cg2(uint32_t d, uint64_t ad, uint64_t bd,
                                               uint32_t idesc, uint32_t acc) {
    asm volatile(
        "{\n\t.reg .pred p;\n\tsetp.ne.u32 p, %5, 0;\n\t"
        "tcgen05.mma.cta_group::2.kind::f16 [%0], %1, %2, %3, "
        "{%4, %4, %4, %4, %4, %4, %4, %4}, p;\n\t}"
        :: "r"(d), "l"(ad), "l"(bd), "r"(idesc), "r"(0u), "r"(acc) : "memory");
}
#endif  // TC_OK

// ---------------------------------------------------------------------------
// Tile configuration: CTA-pair computes 256 rows x full HID; K-chunk = 64.
// 256 threads: warps 0-3 consumers (MMA issue + epilogue), warps 4-7 producers.
// ---------------------------------------------------------------------------
static constexpr int TILE_N   = 512;             // per TMEM pass (2 MMAs of N=256)
static constexpr int TILE_K   = 64;              // one SW128 row = 64 bf16 = 128 B
static constexpr int N_TILES  = HID / TILE_N;    // 4
static constexpr int KC_TILE  = IN_SZ / TILE_K;  // 16 chunks per N-tile
static constexpr int KK_TOT   = N_TILES * KC_TILE;  // 64
static constexpr int STAGES   = 4;

static constexpr uint32_t S_TMEM  = 0;
static constexpr uint32_t S_FULL  = 16;                  // 4 x 8B (on rank 0, count=2)
static constexpr uint32_t S_EMPTY = 48;                  // 4 x 8B (both CTAs, count=1)
static constexpr uint32_t S_DONE  = 80;
static constexpr uint32_t S_EDONE = 88;
static constexpr uint32_t S_B1    = 1024;
static constexpr uint32_t S_W2    = 1024 + 4 * HID;          // 9216
static constexpr uint32_t S_A     = S_W2 + 4 * HID;          // 17408 (1024-aligned)
static constexpr uint32_t A_STAGE_BYTES = 128 * 128;         // 16384
static constexpr uint32_t S_B     = S_A + STAGES * A_STAGE_BYTES;   // 82944
static constexpr uint32_t B_STAGE_BYTES = 256 * 128;         // 32768
static constexpr uint32_t SMEM_BYTES = S_B + STAGES * B_STAGE_BYTES; // 214016

// idesc: dtype=F32(bit4), atype=BF16(bit7), btype=BF16(bit10), N=256, M=256
static constexpr uint32_t IDESC =
    (1u << 4) | (1u << 7) | (1u << 10) | ((256u / 8) << 17) | ((256u / 16) << 24);

// ---------------------------------------------------------------------------
// Fused expert GEMM, cg2, warp-specialized.
// ---------------------------------------------------------------------------
__global__ void __launch_bounds__(256, 1) __cluster_dims__(2, 1, 1)
gemm_fused(const float* __restrict__ b1, const float* __restrict__ W2) {
#if TC_OK
    extern __shared__ __align__(1024) uint8_t smem[];
    const uint32_t sb = smem_to_u32(smem);
    const int tid  = threadIdx.x;
    const int wid  = tid >> 5;
    const uint32_t rank = cluster_rank();
    const int pair = blockIdx.x >> 1;
    const int e    = pair >> 5;                  // 32 pairs per expert
    const int m0p  = (pair & 31) * 256;
    const int m0   = m0p + (int)rank * 128;      // this CTA's 128 rows

    if (wid == 0) TCGEN05_ALLOC_CG2(sb + S_TMEM, 512);
    if (tid == 0) {
        if (rank == 0) {
            for (int s = 0; s < STAGES; s++) MBARRIER_INIT(sb + S_FULL + 8 * s, 2);
            MBARRIER_INIT(sb + S_EDONE, 2);
        }
        for (int s = 0; s < STAGES; s++) MBARRIER_INIT(sb + S_EMPTY + 8 * s, 1);
        MBARRIER_INIT(sb + S_DONE, 1);
    }

    float* s_b1 = (float*)(smem + S_B1);
    float* s_w2 = (float*)(smem + S_W2);
    if (tid < 128) {
        for (int i = tid; i < HID; i += 128) {
            s_b1[i] = __ldg(b1 + (size_t)e * HID + i);
            s_w2[i] = __ldg(W2 + (size_t)e * HID + i);
        }
    }
    __syncthreads();
    CLUSTER_SYNC();   // all barriers initialized cluster-wide before any arrival

    uint32_t tmem;
    asm volatile("ld.shared.b32 %0, [%1];" : "=r"(tmem) : "r"(sb + S_TMEM));

    if (tid >= 128) {
        // =================== PRODUCER WARPS (4-7) ===================
        const int ptid = tid - 128;
        const int c8 = (ptid & 7) * 8;
        const int r0 = ptid >> 3;
        const uint32_t off0 = (uint32_t)(r0 * 128 + (ptid & 7) * 16);
        const uint32_t swz0 = off0 ^ ((off0 >> 3) & 0x70);
        const __nv_bfloat16* pA0 = g_xb + (size_t)(m0 + r0) * IN_SZ + c8;
        const __nv_bfloat16* pB0 = g_w1b + ((size_t)e * HID + (size_t)rank * 128 + r0) * IN_SZ + c8;

        for (int kk = 0; kk < KK_TOT; kk++) {
            const int s = kk & 3;
            const int u = kk >> 2;
            if (u >= 1)
                MBARRIER_WAIT_PARITY(sb + S_EMPTY + 8 * s, (u - 1) & 1);

            // ---- load chunk kk into stage s ----
            {
                const int nt_la = kk >> 4;
                const int kc_la = kk & 15;
                const __nv_bfloat16* pA = pA0 + kc_la * TILE_K;
                uint32_t dA = sb + S_A + (uint32_t)s * A_STAGE_BYTES + swz0;
#pragma unroll
                for (int j = 0; j < 8; j++)
                    cp16(dA + (uint32_t)j * 2048u, pA + (size_t)j * 16 * IN_SZ);
                const __nv_bfloat16* pB = pB0 + ((size_t)nt_la * 512) * IN_SZ + kc_la * TILE_K;
                uint32_t dB = sb + S_B + (uint32_t)s * B_STAGE_BYTES + swz0;
#pragma unroll
                for (int j = 0; j < 16; j++) {
                    const size_t grow = (size_t)((j >> 3) * 256 + (j & 7) * 16) * IN_SZ;
                    cp16(dB + (uint32_t)j * 2048u, pB + grow);
                }
                cp_commit();
            }

            if (kk >= 3) {                       // chunk kk-3 is now resident
                CP_WAIT_GROUP(3);
                FENCE_PROXY_ASYNC_SHARED_CTA();
                NAMED_BAR(1, 128);
                if (ptid == 0) MBARRIER_ARRIVE_RANK0(sb + S_FULL + 8 * ((kk - 3) & 3));
            }
        }
        // drain: chunks 61, 62, 63
        CP_WAIT_GROUP(2);
        FENCE_PROXY_ASYNC_SHARED_CTA();
        NAMED_BAR(1, 128);
        if (ptid == 0) MBARRIER_ARRIVE_RANK0(sb + S_FULL + 8 * (61 & 3));
        CP_WAIT_GROUP(1);
        FENCE_PROXY_ASYNC_SHARED_CTA();
        NAMED_BAR(1, 128);
        if (ptid == 0) MBARRIER_ARRIVE_RANK0(sb + S_FULL + 8 * (62 & 3));
        CP_WAIT_GROUP(0);
        FENCE_PROXY_ASYNC_SHARED_CTA();
        NAMED_BAR(1, 128);
        if (ptid == 0) MBARRIER_ARRIVE_RANK0(sb + S_FULL + 8 * (63 & 3));
    } else {
        // =================== CONSUMER WARPS (0-3) ===================
        const bool leader_warp = (rank == 0) && (wid == 0);
        const uint32_t lead = leader_warp ? elect_one_pred() : 0u;
        float zacc[4] = {0.f, 0.f, 0.f, 0.f};

        for (int nt = 0; nt < N_TILES; nt++) {
            // ---- MMA issue for this tile (rank0 warp0 elected lane) ----
            if (lead) {
                if (nt >= 1)
                    MBARRIER_WAIT_PARITY(sb + S_EDONE, (nt - 1) & 1);
                for (int kc = 0; kc < KC_TILE; kc++) {
                    const int kk = nt * KC_TILE + kc;
                    const int s  = kk & 3;
                    MBARRIER_WAIT_PARITY_CLU(sb + S_FULL + 8 * s, (kk >> 2) & 1);
                    TCGEN05_FENCE_AFTER();
                    const uint64_t ad = MAKE_SMEM_DESC(sb + S_A + (uint32_t)s * A_STAGE_BYTES);
#pragma unroll
                    for (int nh = 0; nh < 2; nh++) {
                        const uint64_t bd = MAKE_SMEM_DESC(sb + S_B + (uint32_t)s * B_STAGE_BYTES
                                                           + (uint32_t)nh * 16384u);
#pragma unroll
                        for (int ks = 0; ks < 4; ks++)
                            mma_f16_ss_cg2(tmem + nh * 256, ad + ks * 2, bd + ks * 2,
                                           IDESC, (uint32_t)((kc | ks) != 0));
                    }
                    TCGEN05_COMMIT_MC_CG2(sb + S_EMPTY + 8 * s, 0x3);
                }
                TCGEN05_COMMIT_MC_CG2(sb + S_DONE, 0x3);
            }
            __syncwarp();

            // ---- epilogue: D[128lanes x 512] -> relu(.+b1) . W2 ----
            MBARRIER_WAIT_PARITY(sb + S_DONE, nt & 1);
            TCGEN05_FENCE_AFTER();

            uint32_t bufA[32], bufB[32];
            TCGEN05_LD_32X32B_X32(bufA, tmem + 0);
            TCGEN05_WAIT_LD();
#pragma unroll
            for (int ch = 0; ch < 16; ch++) {
                // prefetch next chunk while consuming current
                if (ch < 15) {
                    if (ch & 1) { TCGEN05_LD_32X32B_X32(bufA, tmem + (ch + 1) * 32); }
                    else        { TCGEN05_LD_32X32B_X32(bufB, tmem + (ch + 1) * 32); }
                }
                const uint32_t* cur = (ch & 1) ? bufB : bufA;
                const int nb = nt * TILE_N + ch * 32;
#pragma unroll
                for (int q = 0; q < 8; q++) {
                    const float4 bv = *(const float4*)(s_b1 + nb + 4 * q);
                    const float4 wv = *(const float4*)(s_w2 + nb + 4 * q);
                    float h0 = fmaxf(__uint_as_float(cur[4 * q + 0]) + bv.x, 0.f);
                    float h1 = fmaxf(__uint_as_float(cur[4 * q + 1]) + bv.y, 0.f);
                    float h2 = fmaxf(__uint_as_float(cur[4 * q + 2]) + bv.z, 0.f);
                    float h3 = fmaxf(__uint_as_float(cur[4 * q + 3]) + bv.w, 0.f);
                    zacc[0] = fmaf(h0, wv.x, zacc[0]);
                    zacc[1] = fmaf(h1, wv.y, zacc[1]);
                    zacc[2] = fmaf(h2, wv.z, zacc[2]);
                    zacc[3] = fmaf(h3, wv.w, zacc[3]);
                }
                if (ch < 15) TCGEN05_WAIT_LD();
            }
            TCGEN05_FENCE_BEFORE();
            NAMED_BAR(2, 128);                   // all consumers done reading D
            if (tid == 0) MBARRIER_ARRIVE_RANK0(sb + S_EDONE);
        }

        const float z = (zacc[0] + zacc[1]) + (zacc[2] + zacc[3]);
        g_zbuf[(size_t)e * BATCH_SZ + m0 + tid] = z;
    }

    __syncthreads();
    if (wid == 0) {
        TCGEN05_RELINQUISH_CG2();
        TCGEN05_DEALLOC_CG2(tmem, 512);
    }
    CLUSTER_SYNC();   // peer MMAs/multicasts targeting our SMEM must be done
#endif  // TC_OK
}

// ---------------------------------------------------------------------------
// fp32 -> bf16 conversions
// ---------------------------------------------------------------------------
__global__ void cvt_x_kernel(const float4* __restrict__ x) {
    const size_t i = (size_t)blockIdx.x * blockDim.x + threadIdx.x;  // < B*I/4
    const float4 v = x[i];
    __nv_bfloat162* dst = reinterpret_cast<__nv_bfloat162*>(g_xb);
    dst[2 * i]     = __floats2bfloat162_rn(v.x, v.y);
    dst[2 * i + 1] = __floats2bfloat162_rn(v.z, v.w);
}

// W1 [E][K=1024][H=2048] fp32  ->  g_w1b [E][H][K] bf16 (tiled transpose)
__global__ void cvt_w1_kernel(const float* __restrict__ W1) {
    __shared__ float tile[32][33];
    const int e  = blockIdx.z;
    const int h0 = blockIdx.x * 32;
    const int k0 = blockIdx.y * 32;
    const float* src = W1 + (size_t)e * IN_SZ * HID;
#pragma unroll
    for (int j = 0; j < 4; j++) {
        const int k = k0 + threadIdx.y + j * 8;
        tile[threadIdx.y + j * 8][threadIdx.x] = src[(size_t)k * HID + h0 + threadIdx.x];
    }
    __syncthreads();
    __nv_bfloat16* dst = g_w1b + (size_t)e * HID * IN_SZ;
#pragma unroll
    for (int j = 0; j < 4; j++) {
        const int h = h0 + threadIdx.y + j * 8;
        dst[(size_t)h * IN_SZ + k0 + threadIdx.x] =
            __float2bfloat16(tile[threadIdx.x][threadIdx.y + j * 8]);
    }
}

// ---------------------------------------------------------------------------
// Final reduce: out[m] = mean_e sigmoid(z[e][m] + b2[e])
// ---------------------------------------------------------------------------
__global__ void reduce_kernel(const float* __restrict__ b2, float* __restrict__ out) {
    const int i = blockIdx.x * blockDim.x + threadIdx.x;  // < 8192
    float s = 0.f;
#pragma unroll
    for (int ex = 0; ex < N_EXPERTS; ex++) {
        const float z = g_zbuf[(size_t)ex * BATCH_SZ + i] + b2[ex];
        s += 1.f / (1.f + __expf(-z));
    }
    out[i] = s * (1.f / N_EXPERTS);
}

// ---------------------------------------------------------------------------
// Harness entry
// ---------------------------------------------------------------------------
extern "C" void kernel_launch(void* const* d_in, const int* in_sizes, int n_in,
                              void* d_out, int out_size) {
    (void)in_sizes; (void)n_in; (void)out_size;
    const float* x  = (const float*)d_in[0];
    const float* W1 = (const float*)d_in[1];
    const float* b1 = (const float*)d_in[2];
    const float* W2 = (const float*)d_in[3];
    const float* b2 = (const float*)d_in[4];
    float* out = (float*)d_out;

    cudaFuncSetAttribute(gemm_fused, cudaFuncAttributeMaxDynamicSharedMemorySize,
                         (int)SMEM_BYTES);

    cvt_x_kernel<<<(BATCH_SZ * IN_SZ / 4) / 256, 256>>>((const float4*)x);

    dim3 tb(32, 8);
    dim3 tg(HID / 32, IN_SZ / 32, N_EXPERTS);
    cvt_w1_kernel<<<tg, tb>>>(W1);

    // 1920 CTAs = 960 cg2 cluster pairs
    gemm_fused<<<N_EXPERTS * (BATCH_SZ / 256) * 2, 256, SMEM_BYTES>>>(b1, W2);

    reduce_kernel<<<BATCH_SZ / 256, 256>>>(b2, out);
}

// round 9
// speedup vs baseline: 1.0496x; 1.0496x over previous
#include <cuda_runtime.h>
#include <cuda_bf16.h>
#include <cstdint>

// ---------------------------------------------------------------------------
// Arch gate: tcgen05 is sm_103a-ONLY (plain compute_103 phase must compile).
// ---------------------------------------------------------------------------
#if defined(__CUDA_ARCH__) && (__CUDA_ARCH__ == 1030) && defined(__CUDA_ARCH_FEAT_SM103_ALL)
#define TC_OK 1
#else
#define TC_OK 0
#endif

// ---------------------------------------------------------------------------
// Problem constants
// ---------------------------------------------------------------------------
#define N_EXPERTS 30
#define IN_SZ     1024
#define HID       2048
#define BATCH_SZ  8192

#define N_CLUSTERS 74            // 148 CTAs / 2
#define N_WORK     960           // 30 experts * 32 m-blocks of 256

// ---------------------------------------------------------------------------
// Device scratch
// ---------------------------------------------------------------------------
__device__ __align__(16) __nv_bfloat16 g_xb [(size_t)BATCH_SZ * IN_SZ];          // 16 MB
__device__ __align__(16) __nv_bfloat16 g_w1b[(size_t)N_EXPERTS * HID * IN_SZ];   // 126 MB, [E][H][K] K-major
__device__ float g_zbuf[(size_t)N_EXPERTS * BATCH_SZ];                            // 1 MB

// ---------------------------------------------------------------------------
// PTX helpers
// ---------------------------------------------------------------------------
__device__ __forceinline__ uint32_t smem_to_u32(const void* p) {
    uint32_t a;
    asm("{ .reg .u64 t; cvta.to.shared.u64 t, %1; cvt.u32.u64 %0, t; }"
        : "=r"(a) : "l"(p));
    return a;
}

__device__ __forceinline__ uint32_t elect_one_pred() {
    uint32_t pred;
    asm volatile(
        "{\n\t.reg .pred p;\n\telect.sync _|p, 0xFFFFFFFF;\n\tselp.b32 %0, 1, 0, p;\n\t}"
        : "=r"(pred));
    return pred;
}

__device__ __forceinline__ uint32_t cluster_rank() {
    uint32_t r;
    asm("mov.u32 %0, %%cluster_ctarank;" : "=r"(r));
    return r;
}

#define MBARRIER_INIT(addr, cnt) \
    asm volatile("mbarrier.init.shared.b64 [%0], %1;" :: "r"((uint32_t)(addr)), "r"((uint32_t)(cnt)) : "memory")

// local wait, acquire at cta scope
#define MBARRIER_WAIT_PARITY(mbar_smem_addr, phase_parity) do { \
    uint32_t _mbar = (uint32_t)(mbar_smem_addr); \
    uint32_t _parity = (uint32_t)(phase_parity); \
    uint32_t _done; \
    asm volatile( \
        "{\n\t.reg .pred p;\n\t" \
        "mbarrier.try_wait.parity.acquire.cta.shared::cta.b64 p, [%1], %2;\n\t" \
        "selp.b32 %0, 1, 0, p;\n\t}" \
        : "=r"(_done) : "r"(_mbar), "r"(_parity) : "memory"); \
    if (!_done) { \
        asm volatile( \
            "{\n\t.reg .pred P1;\n\t" \
            "WAIT_LOOP_%=:\n\t" \
            "mbarrier.try_wait.parity.acquire.cta.shared::cta.b64 P1, [%0], %1, 0x989680;\n\t" \
            "@P1 bra.uni WAIT_DONE_%=;\n\t" \
            "bra.uni WAIT_LOOP_%=;\n\t" \
            "WAIT_DONE_%=:\n\t}" \
            :: "r"(_mbar), "r"(_parity) : "memory"); \
    } \
} while (0)

// cluster-scope acquire wait (waiting on peer-signaled barriers)
#define MBARRIER_WAIT_PARITY_CLU(mbar_smem_addr, phase_parity) do { \
    uint32_t _mbar = (uint32_t)(mbar_smem_addr); \
    uint32_t _parity = (uint32_t)(phase_parity); \
    uint32_t _done; \
    asm volatile( \
        "{\n\t.reg .pred p;\n\t" \
        "mbarrier.try_wait.parity.acquire.cluster.shared::cta.b64 p, [%1], %2;\n\t" \
        "selp.b32 %0, 1, 0, p;\n\t}" \
        : "=r"(_done) : "r"(_mbar), "r"(_parity) : "memory"); \
    if (!_done) { \
        asm volatile( \
            "{\n\t.reg .pred P1;\n\t" \
            "WAIT_LOOP_%=:\n\t" \
            "mbarrier.try_wait.parity.acquire.cluster.shared::cta.b64 P1, [%0], %1, 0x989680;\n\t" \
            "@P1 bra.uni WAIT_DONE_%=;\n\t" \
            "bra.uni WAIT_LOOP_%=;\n\t" \
            "WAIT_DONE_%=:\n\t}" \
            :: "r"(_mbar), "r"(_parity) : "memory"); \
    } \
} while (0)

// arrive on the same-offset mbarrier in cluster rank 0
#define MBARRIER_ARRIVE_RANK0(local_mbar_addr) \
    asm volatile( \
        "{\n\t.reg .b32 remAddr32;\n\t" \
        "mapa.shared::cluster.u32 remAddr32, %0, 0;\n\t" \
        "mbarrier.arrive.shared::cluster.b64 _, [remAddr32];\n\t}" \
        :: "r"((uint32_t)(local_mbar_addr)) : "memory")

#define CLUSTER_SYNC() do { \
    asm volatile("barrier.cluster.arrive.aligned;" ::: "memory"); \
    asm volatile("barrier.cluster.wait.aligned;" ::: "memory"); \
} while (0)

__device__ __forceinline__ void cp16(uint32_t dst_smem, const void* src_gmem) {
    asm volatile("cp.async.cg.shared.global [%0], [%1], 16;"
                 :: "r"(dst_smem), "l"(src_gmem) : "memory");
}
__device__ __forceinline__ void cp_commit() { asm volatile("cp.async.commit_group;" ::: "memory"); }
#define CP_WAIT_GROUP(n) asm volatile("cp.async.wait_group %0;" :: "n"(n) : "memory")
#define FENCE_PROXY_ASYNC_SHARED_CTA() asm volatile("fence.proxy.async.shared::cta;" ::: "memory")

#if TC_OK
#define TCGEN05_ALLOC_CG2(smem_result_addr, nCols) \
    asm volatile("tcgen05.alloc.cta_group::2.sync.aligned.shared::cta.b32 [%0], %1;" \
        :: "r"((uint32_t)(smem_result_addr)), "r"((uint32_t)(nCols)) : "memory")

#define TCGEN05_DEALLOC_CG2(tmem_addr, nCols) \
    asm volatile("tcgen05.dealloc.cta_group::2.sync.aligned.b32 %0, %1;" \
        :: "r"(tmem_addr), "r"((uint32_t)(nCols)))

#define TCGEN05_RELINQUISH_CG2() \
    asm volatile("tcgen05.relinquish_alloc_permit.cta_group::2.sync.aligned;")

#define TCGEN05_COMMIT_MC_CG2(mbar_smem_addr, cta_mask) \
    asm volatile("tcgen05.commit.cta_group::2.mbarrier::arrive::one.shared::cluster.multicast::cluster.b64 [%0], %1;" \
        :: "r"((uint32_t)(mbar_smem_addr)), "h"((uint16_t)(cta_mask)) : "memory")

#define TCGEN05_WAIT_LD()  asm volatile("tcgen05.wait::ld.sync.aligned;" ::: "memory")
#define TCGEN05_FENCE_BEFORE() asm volatile("tcgen05.fence::before_thread_sync;" ::: "memory")
#define TCGEN05_FENCE_AFTER()  asm volatile("tcgen05.fence::after_thread_sync;" ::: "memory")

#define TCGEN05_LD_32X32B_X32(r, tmem_addr) \
    asm volatile( \
        "tcgen05.ld.sync.aligned.32x32b.x32.b32 " \
        "{%0, %1, %2, %3, %4, %5, %6, %7, " \
        " %8, %9, %10, %11, %12, %13, %14, %15, " \
        " %16, %17, %18, %19, %20, %21, %22, %23, " \
        " %24, %25, %26, %27, %28, %29, %30, %31}, [%32];" \
        : "=r"((r)[0]),  "=r"((r)[1]),  "=r"((r)[2]),  "=r"((r)[3]), \
          "=r"((r)[4]),  "=r"((r)[5]),  "=r"((r)[6]),  "=r"((r)[7]), \
          "=r"((r)[8]),  "=r"((r)[9]),  "=r"((r)[10]), "=r"((r)[11]), \
          "=r"((r)[12]), "=r"((r)[13]), "=r"((r)[14]), "=r"((r)[15]), \
          "=r"((r)[16]), "=r"((r)[17]), "=r"((r)[18]), "=r"((r)[19]), \
          "=r"((r)[20]), "=r"((r)[21]), "=r"((r)[22]), "=r"((r)[23]), \
          "=r"((r)[24]), "=r"((r)[25]), "=r"((r)[26]), "=r"((r)[27]), \
          "=r"((r)[28]), "=r"((r)[29]), "=r"((r)[30]), "=r"((r)[31]) \
        : "r"(tmem_addr))

// SW128 K-major SMEM descriptor (layout=SW128, Blackwell version=1, LBO=1, SBO=64)
static constexpr uint64_t SMEM_DESC_BASE_SW128 =
    (uint64_t(2) << 61) | (uint64_t(1) << 46) | (uint64_t(64) << 32) | (uint64_t(1) << 16);
#define MAKE_SMEM_DESC(base_addr) \
    (SMEM_DESC_BASE_SW128 | ((uint64_t)((base_addr) >> 4) & 0x3FFF))

// cg2 bf16 SS MMA, fp32 D: D[256,N] += A[256,k16] * B[N,k16]^T
__device__ __forceinline__ void mma_f16_ss_cg2(uint32_t d, uint64_t ad, uint64_t bd,
                                               uint32_t idesc, uint32_t acc) {
    asm volatile(
        "{\n\t.reg .pred p;\n\tsetp.ne.u32 p, %5, 0;\n\t"
        "tcgen05.mma.cta_group::2.kind::f16 [%0], %1, %2, %3, "
        "{%4, %4, %4, %4, %4, %4, %4, %4}, p;\n\t}"
        :: "r"(d), "l"(ad), "l"(bd), "r"(idesc), "r"(0u), "r"(acc) : "memory");
}
#endif  // TC_OK

// ---------------------------------------------------------------------------
// Persistent cg2 GEMM. 74 clusters; each iterates 12-13 work items
// (expert, 256-row m-block) through ONE flat global chunk loop.
// Global indices keep every mbarrier parity formula identical to the
// proven R3/R4 machinery (all per-work-item counts are even).
// ---------------------------------------------------------------------------
static constexpr int TILE_N   = 512;
static constexpr int TILE_K   = 64;
static constexpr int STAGES   = 4;

static constexpr uint32_t S_TMEM  = 0;
static constexpr uint32_t S_FULL  = 16;                  // 4 x 8B (rank0, count=2)
static constexpr uint32_t S_EMPTY = 48;                  // 4 x 8B (both, count=1)
static constexpr uint32_t S_DONE  = 80;                  // both (commit-mc)
static constexpr uint32_t S_EDONE = 88;                  // rank0, count=2
static constexpr uint32_t S_B1    = 1024;
static constexpr uint32_t S_W2    = 1024 + 4 * HID;          // 9216
static constexpr uint32_t S_A     = S_W2 + 4 * HID;          // 17408
static constexpr uint32_t A_STAGE_BYTES = 128 * 128;         // 16384
static constexpr uint32_t S_B     = S_A + STAGES * A_STAGE_BYTES;  // 82944
static constexpr uint32_t B_STAGE_BYTES = 256 * 128;         // 32768
static constexpr uint32_t SMEM_BYTES = S_B + STAGES * B_STAGE_BYTES; // 214016

// idesc: dtype=F32(bit4), atype=BF16(bit7), btype=BF16(bit10), N=256, M=256
static constexpr uint32_t IDESC =
    (1u << 4) | (1u << 7) | (1u << 10) | ((256u / 8) << 17) | ((256u / 16) << 24);

__global__ void __launch_bounds__(128, 1) __cluster_dims__(2, 1, 1)
gemm_fused(const float* __restrict__ b1, const float* __restrict__ W2) {
#if TC_OK
    extern __shared__ __align__(1024) uint8_t smem[];
    const uint32_t sb = smem_to_u32(smem);
    const int tid  = threadIdx.x;
    const int wid  = tid >> 5;
    const uint32_t rank = cluster_rank();
    const int cid  = blockIdx.x >> 1;              // cluster id 0..73

    // work items for this cluster: wk = cid + 74*i
    const int nwork = (N_WORK - cid + N_CLUSTERS - 1) / N_CLUSTERS;  // 13 or 12
    const int KKT   = nwork * 64;                  // total chunks, flat

    if (wid == 0) TCGEN05_ALLOC_CG2(sb + S_TMEM, 512);
    if (tid == 0) {
        if (rank == 0) {
            for (int s = 0; s < STAGES; s++) MBARRIER_INIT(sb + S_FULL + 8 * s, 2);
            MBARRIER_INIT(sb + S_EDONE, 2);
        }
        for (int s = 0; s < STAGES; s++) MBARRIER_INIT(sb + S_EMPTY + 8 * s, 1);
        MBARRIER_INIT(sb + S_DONE, 1);
    }

    float* s_b1 = (float*)(smem + S_B1);
    float* s_w2 = (float*)(smem + S_W2);
    {   // b1/W2 for first work item
        const int e0 = cid >> 5;
        for (int i = tid; i < HID; i += 128) {
            s_b1[i] = __ldg(b1 + (size_t)e0 * HID + i);
            s_w2[i] = __ldg(W2 + (size_t)e0 * HID + i);
        }
    }
    __syncthreads();
    CLUSTER_SYNC();   // barriers initialized cluster-wide before any arrival

    uint32_t tmem;
    asm volatile("ld.shared.b32 %0, [%1];" : "=r"(tmem) : "r"(sb + S_TMEM));

    // per-thread cp.async geometry: thread t -> 16B column (t&7), base row (t>>3)
    const int c8 = (tid & 7) * 8;
    const int r0 = tid >> 3;
    const uint32_t off0 = (uint32_t)(r0 * 128 + (tid & 7) * 16);
    const uint32_t swz0 = off0 ^ ((off0 >> 3) & 0x70);

    // load chunk with FLAT index la into stage la&3 (pointers derived per-chunk)
    auto load_chunk = [&](int la) {
        const int wk   = cid + N_CLUSTERS * (la >> 6);     // work item
        const int e_la = wk >> 5;
        const int m0_la = (wk & 31) * 256 + (int)rank * 128;
        const int nt_la = (la >> 4) & 3;
        const int kc_la = la & 15;
        const int s     = la & 3;
        const __nv_bfloat16* pA = g_xb + (size_t)(m0_la + r0) * IN_SZ + c8 + kc_la * TILE_K;
        uint32_t dA = sb + S_A + (uint32_t)s * A_STAGE_BYTES + swz0;
#pragma unroll
        for (int j = 0; j < 8; j++)                         // A rows r0+16j (0..127)
            cp16(dA + (uint32_t)j * 2048u, pA + (size_t)j * 16 * IN_SZ);
        const __nv_bfloat16* pB = g_w1b
            + ((size_t)e_la * HID + (size_t)rank * 128 + (size_t)nt_la * 512 + r0) * IN_SZ
            + c8 + kc_la * TILE_K;
        uint32_t dB = sb + S_B + (uint32_t)s * B_STAGE_BYTES + swz0;
#pragma unroll
        for (int j = 0; j < 16; j++) {                      // B local rows (2 nh halves)
            const size_t grow = (size_t)((j >> 3) * 256 + (j & 7) * 16) * IN_SZ;
            cp16(dB + (uint32_t)j * 2048u, pB + grow);
        }
        cp_commit();
    };

    // prologue: chunks 0,1,2 -> stages 0,1,2
    load_chunk(0);
    load_chunk(1);
    load_chunk(2);

    const bool leader_warp = (rank == 0) && (wid == 0);
    const uint32_t lead = leader_warp ? elect_one_pred() : 0u;
    float zacc[4] = {0.f, 0.f, 0.f, 0.f};

    for (int kk = 0; kk < KKT; kk++) {
        const int t  = kk >> 4;        // GLOBAL tile index (0..4*nwork-1)
        const int kc = kk & 15;
        const int s  = kk & 3;

        // ---- producer step: load chunk kk+3 ----
        const int la = kk + 3;
        if (la < KKT) {
            const int u = la >> 2;     // global use index of stage la&3
            if (u >= 1)
                MBARRIER_WAIT_PARITY(sb + S_EMPTY + 8 * (la & 3), (u - 1) & 1);
            load_chunk(la);
            CP_WAIT_GROUP(3);          // chunk kk fully resident
        } else {
            CP_WAIT_GROUP(0);
        }
        FENCE_PROXY_ASYNC_SHARED_CTA();
        __syncthreads();
        if (tid == 0) MBARRIER_ARRIVE_RANK0(sb + S_FULL + 8 * s);

        // ---- leader: issue MMAs for chunk kk ----
        if (lead) {
            if (kc == 0 && t >= 1)     // D reuse: both epilogues of tile t-1 done
                MBARRIER_WAIT_PARITY_CLU(sb + S_EDONE, (t - 1) & 1);
            MBARRIER_WAIT_PARITY_CLU(sb + S_FULL + 8 * s, (kk >> 2) & 1);
            TCGEN05_FENCE_AFTER();
            const uint64_t ad = MAKE_SMEM_DESC(sb + S_A + (uint32_t)s * A_STAGE_BYTES);
#pragma unroll
            for (int nh = 0; nh < 2; nh++) {
                const uint64_t bd = MAKE_SMEM_DESC(sb + S_B + (uint32_t)s * B_STAGE_BYTES
                                                   + (uint32_t)nh * 16384u);
#pragma unroll
                for (int ks = 0; ks < 4; ks++)
                    mma_f16_ss_cg2(tmem + nh * 256, ad + ks * 2, bd + ks * 2,
                                   IDESC, (uint32_t)((kc | ks) != 0));
            }
            TCGEN05_COMMIT_MC_CG2(sb + S_EMPTY + 8 * s, 0x3);
            if (kc == 15) TCGEN05_COMMIT_MC_CG2(sb + S_DONE, 0x3);
        }

        // ---- epilogue at end of each tile (all 128 threads) ----
        if (kc == 15) {
            MBARRIER_WAIT_PARITY(sb + S_DONE, t & 1);
            TCGEN05_FENCE_AFTER();

            uint32_t bufA[32], bufB[32];
            TCGEN05_LD_32X32B_X32(bufA, tmem + 0);
            TCGEN05_WAIT_LD();
#pragma unroll
            for (int ch = 0; ch < 16; ch++) {
                if (ch < 15) {          // prefetch next chunk while consuming current
                    if (ch & 1) { TCGEN05_LD_32X32B_X32(bufA, tmem + (ch + 1) * 32); }
                    else        { TCGEN05_LD_32X32B_X32(bufB, tmem + (ch + 1) * 32); }
                }
                const uint32_t* cur = (ch & 1) ? bufB : bufA;
                const int nb = (t & 3) * TILE_N + ch * 32;
#pragma unroll
                for (int c = 0; c < 32; c++) {
                    float h = __uint_as_float(cur[c]) + s_b1[nb + c];
                    h = fmaxf(h, 0.f);
                    zacc[c & 3] = fmaf(h, s_w2[nb + c], zacc[c & 3]);
                }
                if (ch < 15) TCGEN05_WAIT_LD();
            }
            TCGEN05_FENCE_BEFORE();
            __syncthreads();            // whole CTA consumed D
            if (tid == 0) MBARRIER_ARRIVE_RANK0(sb + S_EDONE);

            if ((t & 3) == 3) {
                // ---- end of work item: emit z, reset, load next b1/W2 ----
                const int w  = t >> 2;
                const int wk = cid + N_CLUSTERS * w;
                const int e_w = wk >> 5;
                const int m0w = (wk & 31) * 256 + (int)rank * 128;
                const float z = (zacc[0] + zacc[1]) + (zacc[2] + zacc[3]);
                g_zbuf[(size_t)e_w * BATCH_SZ + m0w + tid] = z;
                zacc[0] = zacc[1] = zacc[2] = zacc[3] = 0.f;

                if (w + 1 < nwork) {
                    const int e_n = (cid + N_CLUSTERS * (w + 1)) >> 5;
                    for (int i = tid; i < HID; i += 128) {
                        s_b1[i] = __ldg(b1 + (size_t)e_n * HID + i);
                        s_w2[i] = __ldg(W2 + (size_t)e_n * HID + i);
                    }
                }
                __syncthreads();        // reload visible before next tile's epilogue
            }
        }
    }

    __syncthreads();
    if (wid == 0) {
        TCGEN05_RELINQUISH_CG2();
        TCGEN05_DEALLOC_CG2(tmem, 512);
    }
    CLUSTER_SYNC();   // peer MMAs/multicasts targeting our SMEM must be done
#endif  // TC_OK
}

// ---------------------------------------------------------------------------
// fp32 -> bf16 conversions (proven)
// ---------------------------------------------------------------------------
__global__ void cvt_x_kernel(const float4* __restrict__ x) {
    const size_t i = (size_t)blockIdx.x * blockDim.x + threadIdx.x;  // < B*I/4
    const float4 v = x[i];
    __nv_bfloat162* dst = reinterpret_cast<__nv_bfloat162*>(g_xb);
    dst[2 * i]     = __floats2bfloat162_rn(v.x, v.y);
    dst[2 * i + 1] = __floats2bfloat162_rn(v.z, v.w);
}

// W1 [E][K=1024][H=2048] fp32  ->  g_w1b [E][H][K] bf16 (tiled transpose)
__global__ void cvt_w1_kernel(const float* __restrict__ W1) {
    __shared__ float tile[32][33];
    const int e  = blockIdx.z;
    const int h0 = blockIdx.x * 32;
    const int k0 = blockIdx.y * 32;
    const float* src = W1 + (size_t)e * IN_SZ * HID;
#pragma unroll
    for (int j = 0; j < 4; j++) {
        const int k = k0 + threadIdx.y + j * 8;
        tile[threadIdx.y + j * 8][threadIdx.x] = src[(size_t)k * HID + h0 + threadIdx.x];
    }
    __syncthreads();
    __nv_bfloat16* dst = g_w1b + (size_t)e * HID * IN_SZ;
#pragma unroll
    for (int j = 0; j < 4; j++) {
        const int h = h0 + threadIdx.y + j * 8;
        dst[(size_t)h * IN_SZ + k0 + threadIdx.x] =
            __float2bfloat16(tile[threadIdx.x][threadIdx.y + j * 8]);
    }
}

// ---------------------------------------------------------------------------
// Final reduce: out[m] = mean_e sigmoid(z[e][m] + b2[e])
// ---------------------------------------------------------------------------
__global__ void reduce_kernel(const float* __restrict__ b2, float* __restrict__ out) {
    const int i = blockIdx.x * blockDim.x + threadIdx.x;  // < 8192
    float s = 0.f;
#pragma unroll
    for (int ex = 0; ex < N_EXPERTS; ex++) {
        const float z = g_zbuf[(size_t)ex * BATCH_SZ + i] + b2[ex];
        s += 1.f / (1.f + __expf(-z));
    }
    out[i] = s * (1.f / N_EXPERTS);
}

// ---------------------------------------------------------------------------
// Harness entry
// ---------------------------------------------------------------------------
extern "C" void kernel_launch(void* const* d_in, const int* in_sizes, int n_in,
                              void* d_out, int out_size) {
    (void)in_sizes; (void)n_in; (void)out_size;
    const float* x  = (const float*)d_in[0];
    const float* W1 = (const float*)d_in[1];
    const float* b1 = (const float*)d_in[2];
    const float* W2 = (const float*)d_in[3];
    const float* b2 = (const float*)d_in[4];
    float* out = (float*)d_out;

    cudaFuncSetAttribute(gemm_fused, cudaFuncAttributeMaxDynamicSharedMemorySize,
                         (int)SMEM_BYTES);

    cvt_x_kernel<<<(BATCH_SZ * IN_SZ / 4) / 256, 256>>>((const float4*)x);

    dim3 tb(32, 8);
    dim3 tg(HID / 32, IN_SZ / 32, N_EXPERTS);
    cvt_w1_kernel<<<tg, tb>>>(W1);

    // persistent: 148 CTAs = 74 cg2 clusters, 12-13 work items each
    gemm_fused<<<2 * N_CLUSTERS, 128, SMEM_BYTES>>>(b1, W2);

    reduce_kernel<<<BATCH_SZ / 256, 256>>>(b2, out);
}

// round 11
// speedup vs baseline: 1.5617x; 1.4879x over previous
#include <cuda_runtime.h>
#include <cuda_bf16.h>
#include <cstdint>

// ---------------------------------------------------------------------------
// Arch gate: tcgen05 is sm_103a-ONLY (plain compute_103 phase must compile).
// ---------------------------------------------------------------------------
#if defined(__CUDA_ARCH__) && (__CUDA_ARCH__ == 1030) && defined(__CUDA_ARCH_FEAT_SM103_ALL)
#define TC_OK 1
#else
#define TC_OK 0
#endif

// ---------------------------------------------------------------------------
// Problem constants
// ---------------------------------------------------------------------------
#define N_EXPERTS 30
#define IN_SZ     1024
#define HID       2048
#define BATCH_SZ  8192

#define N_CLUSTERS 74            // 148 CTAs / 2
#define N_WORK     960           // 30 experts * 32 m-blocks of 256

// ---------------------------------------------------------------------------
// Device scratch.
// g_xa: A blobs. blob(mb128, kc) = 16KB SW128-swizzled SMEM image of
//       x rows [mb*128, +128), k cols [kc*64, +64) bf16.
// g_wb: B blobs. blob(e, nt, rank, kc) = 32KB image: local row lr = nh*128+row,
//       hid = nt*512 + nh*256 + rank*128 + row, k cols [kc*64, +64).
// ---------------------------------------------------------------------------
__device__ __align__(16) __nv_bfloat16 g_xa[(size_t)BATCH_SZ * IN_SZ];           // 16 MB
__device__ __align__(16) __nv_bfloat16 g_wb[(size_t)N_EXPERTS * HID * IN_SZ];    // 126 MB
__device__ float g_zbuf[(size_t)N_EXPERTS * BATCH_SZ];                            // 1 MB

// ---------------------------------------------------------------------------
// PTX helpers
// ---------------------------------------------------------------------------
__device__ __forceinline__ uint32_t smem_to_u32(const void* p) {
    uint32_t a;
    asm("{ .reg .u64 t; cvta.to.shared.u64 t, %1; cvt.u32.u64 %0, t; }"
        : "=r"(a) : "l"(p));
    return a;
}

__device__ __forceinline__ uint32_t elect_one_pred() {
    uint32_t pred;
    asm volatile(
        "{\n\t.reg .pred p;\n\telect.sync _|p, 0xFFFFFFFF;\n\tselp.b32 %0, 1, 0, p;\n\t}"
        : "=r"(pred));
    return pred;
}

__device__ __forceinline__ uint32_t cluster_rank() {
    uint32_t r;
    asm("mov.u32 %0, %%cluster_ctarank;" : "=r"(r));
    return r;
}

#define MBARRIER_INIT(addr, cnt) \
    asm volatile("mbarrier.init.shared.b64 [%0], %1;" :: "r"((uint32_t)(addr)), "r"((uint32_t)(cnt)) : "memory")

#define MBARRIER_EXPECT_TX(addr, bytes) \
    asm volatile("mbarrier.arrive.expect_tx.shared.b64 _, [%0], %1;" \
        :: "r"((uint32_t)(addr)), "r"((uint32_t)(bytes)) : "memory")

// local wait, acquire at cta scope
#define MBARRIER_WAIT_PARITY(mbar_smem_addr, phase_parity) do { \
    uint32_t _mbar = (uint32_t)(mbar_smem_addr); \
    uint32_t _parity = (uint32_t)(phase_parity); \
    uint32_t _done; \
    asm volatile( \
        "{\n\t.reg .pred p;\n\t" \
        "mbarrier.try_wait.parity.acquire.cta.shared::cta.b64 p, [%1], %2;\n\t" \
        "selp.b32 %0, 1, 0, p;\n\t}" \
        : "=r"(_done) : "r"(_mbar), "r"(_parity) : "memory"); \
    if (!_done) { \
        asm volatile( \
            "{\n\t.reg .pred P1;\n\t" \
            "WAIT_LOOP_%=:\n\t" \
            "mbarrier.try_wait.parity.acquire.cta.shared::cta.b64 P1, [%0], %1, 0x989680;\n\t" \
            "@P1 bra.uni WAIT_DONE_%=;\n\t" \
            "bra.uni WAIT_LOOP_%=;\n\t" \
            "WAIT_DONE_%=:\n\t}" \
            :: "r"(_mbar), "r"(_parity) : "memory"); \
    } \
} while (0)

// cluster-scope acquire wait (peer-signaled barriers / peer data)
#define MBARRIER_WAIT_PARITY_CLU(mbar_smem_addr, phase_parity) do { \
    uint32_t _mbar = (uint32_t)(mbar_smem_addr); \
    uint32_t _parity = (uint32_t)(phase_parity); \
    uint32_t _done; \
    asm volatile( \
        "{\n\t.reg .pred p;\n\t" \
        "mbarrier.try_wait.parity.acquire.cluster.shared::cta.b64 p, [%1], %2;\n\t" \
        "selp.b32 %0, 1, 0, p;\n\t}" \
        : "=r"(_done) : "r"(_mbar), "r"(_parity) : "memory"); \
    if (!_done) { \
        asm volatile( \
            "{\n\t.reg .pred P1;\n\t" \
            "WAIT_LOOP_%=:\n\t" \
            "mbarrier.try_wait.parity.acquire.cluster.shared::cta.b64 P1, [%0], %1, 0x989680;\n\t" \
            "@P1 bra.uni WAIT_DONE_%=;\n\t" \
            "bra.uni WAIT_LOOP_%=;\n\t" \
            "WAIT_DONE_%=:\n\t}" \
            :: "r"(_mbar), "r"(_parity) : "memory"); \
    } \
} while (0)

// arrive on the same-offset mbarrier in cluster rank 0
#define MBARRIER_ARRIVE_RANK0(local_mbar_addr) \
    asm volatile( \
        "{\n\t.reg .b32 remAddr32;\n\t" \
        "mapa.shared::cluster.u32 remAddr32, %0, 0;\n\t" \
        "mbarrier.arrive.shared::cluster.b64 _, [remAddr32];\n\t}" \
        :: "r"((uint32_t)(local_mbar_addr)) : "memory")

#define CLUSTER_SYNC() do { \
    asm volatile("barrier.cluster.arrive.aligned;" ::: "memory"); \
    asm volatile("barrier.cluster.wait.aligned;" ::: "memory"); \
} while (0)

#define NAMED_BAR(id, cnt) \
    asm volatile("bar.sync %0, %1;" :: "r"(id), "r"(cnt) : "memory")

// bulk async copy global -> own-CTA shared, completion on LOCAL mbarrier
#define CP_BULK_G2S(dst_smem, src_gmem, bytes, mbar) \
    asm volatile("cp.async.bulk.shared::cluster.global.mbarrier::complete_tx::bytes " \
                 "[%0], [%1], %2, [%3];" \
        :: "r"((uint32_t)(dst_smem)), "l"(src_gmem), "r"((uint32_t)(bytes)), \
           "r"((uint32_t)(mbar)) : "memory")

#if TC_OK
#define TCGEN05_ALLOC_CG2(smem_result_addr, nCols) \
    asm volatile("tcgen05.alloc.cta_group::2.sync.aligned.shared::cta.b32 [%0], %1;" \
        :: "r"((uint32_t)(smem_result_addr)), "r"((uint32_t)(nCols)) : "memory")

#define TCGEN05_DEALLOC_CG2(tmem_addr, nCols) \
    asm volatile("tcgen05.dealloc.cta_group::2.sync.aligned.b32 %0, %1;" \
        :: "r"(tmem_addr), "r"((uint32_t)(nCols)))

#define TCGEN05_RELINQUISH_CG2() \
    asm volatile("tcgen05.relinquish_alloc_permit.cta_group::2.sync.aligned;")

#define TCGEN05_COMMIT_MC_CG2(mbar_smem_addr, cta_mask) \
    asm volatile("tcgen05.commit.cta_group::2.mbarrier::arrive::one.shared::cluster.multicast::cluster.b64 [%0], %1;" \
        :: "r"((uint32_t)(mbar_smem_addr)), "h"((uint16_t)(cta_mask)) : "memory")

#define TCGEN05_WAIT_LD()  asm volatile("tcgen05.wait::ld.sync.aligned;" ::: "memory")
#define TCGEN05_FENCE_BEFORE() asm volatile("tcgen05.fence::before_thread_sync;" ::: "memory")
#define TCGEN05_FENCE_AFTER()  asm volatile("tcgen05.fence::after_thread_sync;" ::: "memory")

#define TCGEN05_LD_32X32B_X32(r, tmem_addr) \
    asm volatile( \
        "tcgen05.ld.sync.aligned.32x32b.x32.b32 " \
        "{%0, %1, %2, %3, %4, %5, %6, %7, " \
        " %8, %9, %10, %11, %12, %13, %14, %15, " \
        " %16, %17, %18, %19, %20, %21, %22, %23, " \
        " %24, %25, %26, %27, %28, %29, %30, %31}, [%32];" \
        : "=r"((r)[0]),  "=r"((r)[1]),  "=r"((r)[2]),  "=r"((r)[3]), \
          "=r"((r)[4]),  "=r"((r)[5]),  "=r"((r)[6]),  "=r"((r)[7]), \
          "=r"((r)[8]),  "=r"((r)[9]),  "=r"((r)[10]), "=r"((r)[11]), \
          "=r"((r)[12]), "=r"((r)[13]), "=r"((r)[14]), "=r"((r)[15]), \
          "=r"((r)[16]), "=r"((r)[17]), "=r"((r)[18]), "=r"((r)[19]), \
          "=r"((r)[20]), "=r"((r)[21]), "=r"((r)[22]), "=r"((r)[23]), \
          "=r"((r)[24]), "=r"((r)[25]), "=r"((r)[26]), "=r"((r)[27]), \
          "=r"((r)[28]), "=r"((r)[29]), "=r"((r)[30]), "=r"((r)[31]) \
        : "r"(tmem_addr))

// SW128 K-major SMEM descriptor (layout=SW128, Blackwell version=1, LBO=1, SBO=64)
static constexpr uint64_t SMEM_DESC_BASE_SW128 =
    (uint64_t(2) << 61) | (uint64_t(1) << 46) | (uint64_t(64) << 32) | (uint64_t(1) << 16);
#define MAKE_SMEM_DESC(base_addr) \
    (SMEM_DESC_BASE_SW128 | ((uint64_t)((base_addr) >> 4) & 0x3FFF))

// cg2 bf16 SS MMA, fp32 D: D[256,N] += A[256,k16] * B[N,k16]^T
__device__ __forceinline__ void mma_f16_ss_cg2(uint32_t d, uint64_t ad, uint64_t bd,
                                               uint32_t idesc, uint32_t acc) {
    asm volatile(
        "{\n\t.reg .pred p;\n\tsetp.ne.u32 p, %5, 0;\n\t"
        "tcgen05.mma.cta_group::2.kind::f16 [%0], %1, %2, %3, "
        "{%4, %4, %4, %4, %4, %4, %4, %4}, p;\n\t}"
        :: "r"(d), "l"(ad), "l"(bd), "r"(idesc), "r"(0u), "r"(acc) : "memory");
}
#endif  // TC_OK

// ---------------------------------------------------------------------------
// Persistent cg2 GEMM, tx-tracked bulk producers with LOCAL completion
// barriers + lag-1 relay to rank0's combined FULL barrier.
// 192 threads: w0-3 epilogue, w4 producer lane, w5 MMA-issue lane (rank0).
// ---------------------------------------------------------------------------
static constexpr int TILE_N   = 512;
static constexpr int STAGES   = 4;

static constexpr uint32_t S_TMEM  = 0;
static constexpr uint32_t S_FULLL = 16;                  // 4 x 8B per CTA (local tx)
static constexpr uint32_t S_FULLC = 48;                  // 4 x 8B rank0 (cnt=2 relays)
static constexpr uint32_t S_EMPTY = 80;                  // 4 x 8B per CTA (cnt=1)
static constexpr uint32_t S_DONE  = 112;                 // per CTA (commit-mc)
static constexpr uint32_t S_EDONE = 120;                 // rank0, cnt=2
static constexpr uint32_t S_B1    = 1024;
static constexpr uint32_t S_W2    = 1024 + 4 * HID;          // 9216
static constexpr uint32_t S_A     = S_W2 + 4 * HID;          // 17408 (1024-aligned)
static constexpr uint32_t A_STAGE_BYTES = 16384;
static constexpr uint32_t S_B     = S_A + STAGES * A_STAGE_BYTES;  // 82944
static constexpr uint32_t B_STAGE_BYTES = 32768;
static constexpr uint32_t SMEM_BYTES = S_B + STAGES * B_STAGE_BYTES; // 214016
static constexpr uint32_t TXL_BYTES = A_STAGE_BYTES + B_STAGE_BYTES; // 49152 local

// idesc: dtype=F32(bit4), atype=BF16(bit7), btype=BF16(bit10), N=256, M=256
static constexpr uint32_t IDESC =
    (1u << 4) | (1u << 7) | (1u << 10) | ((256u / 8) << 17) | ((256u / 16) << 24);

__global__ void __launch_bounds__(192, 1) __cluster_dims__(2, 1, 1)
gemm_fused(const float* __restrict__ b1, const float* __restrict__ W2) {
#if TC_OK
    extern __shared__ __align__(1024) uint8_t smem[];
    const uint32_t sb = smem_to_u32(smem);
    const int tid  = threadIdx.x;
    const int wid  = tid >> 5;
    const uint32_t rank = cluster_rank();
    const int cid  = blockIdx.x >> 1;              // cluster id 0..73

    const int nwork = (N_WORK - cid + N_CLUSTERS - 1) / N_CLUSTERS;  // 13 or 12
    const int KKT   = nwork * 64;                  // total chunks, flat
    const int NTT   = nwork * 4;                   // total tiles, flat

    if (wid == 0) TCGEN05_ALLOC_CG2(sb + S_TMEM, 512);
    if (tid == 0) {
        if (rank == 0) {
            for (int s = 0; s < STAGES; s++) MBARRIER_INIT(sb + S_FULLC + 8 * s, 2);
            MBARRIER_INIT(sb + S_EDONE, 2);
        }
        for (int s = 0; s < STAGES; s++) {
            MBARRIER_INIT(sb + S_FULLL + 8 * s, 1);   // expect_tx arms each phase
            MBARRIER_INIT(sb + S_EMPTY + 8 * s, 1);
        }
        MBARRIER_INIT(sb + S_DONE, 1);
    }

    float* s_b1 = (float*)(smem + S_B1);
    float* s_w2 = (float*)(smem + S_W2);
    if (tid < 128) {
        const int e0 = cid >> 5;
        for (int i = tid; i < HID; i += 128) {
            s_b1[i] = __ldg(b1 + (size_t)e0 * HID + i);
            s_w2[i] = __ldg(W2 + (size_t)e0 * HID + i);
        }
    }
    __syncthreads();
    CLUSTER_SYNC();   // barriers initialized cluster-wide before any arrival/tx

    uint32_t tmem;
    asm volatile("ld.shared.b32 %0, [%1];" : "=r"(tmem) : "r"(sb + S_TMEM));

    if (wid == 4) {
        // =================== PRODUCER LANE (both CTAs) ===================
        if (elect_one_pred()) {
            const char* xa = (const char*)g_xa;
            const char* wb = (const char*)g_wb;

            for (int la = 0; la < KKT; la++) {
                const int s = la & 3;
                const int u = la >> 2;
                if (u >= 1)
                    MBARRIER_WAIT_PARITY(sb + S_EMPTY + 8 * s, (u - 1) & 1);

                const int wk = cid + N_CLUSTERS * (la >> 6);
                const int kc = la & 15;
                const int nt = (la >> 4) & 3;
                const int e_la = wk >> 5;
                const int mb   = (wk & 31) * 2 + (int)rank;   // m-block of 128

                // arm local barrier for this stage's phase, then 2 local bulks
                MBARRIER_EXPECT_TX(sb + S_FULLL + 8 * s, TXL_BYTES);
                const size_t aoff = ((size_t)(mb * 16 + kc)) << 14;
                CP_BULK_G2S(sb + S_A + (uint32_t)s * A_STAGE_BYTES,
                            xa + aoff, A_STAGE_BYTES, sb + S_FULLL + 8 * s);
                const size_t boff = ((size_t)(((e_la * 4 + nt) * 2 + (int)rank) * 16 + kc)) << 15;
                CP_BULK_G2S(sb + S_B + (uint32_t)s * B_STAGE_BYTES,
                            wb + boff, B_STAGE_BYTES, sb + S_FULLL + 8 * s);

                // relay previous chunk's completion to rank0's combined barrier
                if (la >= 1) {
                    const int p = la - 1;
                    MBARRIER_WAIT_PARITY(sb + S_FULLL + 8 * (p & 3), (p >> 2) & 1);
                    MBARRIER_ARRIVE_RANK0(sb + S_FULLC + 8 * (p & 3));
                }
            }
            // relay final chunk
            const int p = KKT - 1;
            MBARRIER_WAIT_PARITY(sb + S_FULLL + 8 * (p & 3), (p >> 2) & 1);
            MBARRIER_ARRIVE_RANK0(sb + S_FULLC + 8 * (p & 3));
        }
    } else if (wid == 5) {
        // =================== MMA ISSUE LANE (rank 0 only) ===================
        if (rank == 0 && elect_one_pred()) {
            for (int t = 0; t < NTT; t++) {
                if (t >= 1)
                    MBARRIER_WAIT_PARITY_CLU(sb + S_EDONE, (t - 1) & 1);
                for (int kc = 0; kc < 16; kc++) {
                    const int kk = t * 16 + kc;
                    const int s  = kk & 3;
                    MBARRIER_WAIT_PARITY_CLU(sb + S_FULLC + 8 * s, (kk >> 2) & 1);
                    TCGEN05_FENCE_AFTER();
                    const uint64_t ad = MAKE_SMEM_DESC(sb + S_A + (uint32_t)s * A_STAGE_BYTES);
#pragma unroll
                    for (int nh = 0; nh < 2; nh++) {
                        const uint64_t bd = MAKE_SMEM_DESC(sb + S_B + (uint32_t)s * B_STAGE_BYTES
                                                           + (uint32_t)nh * 16384u);
#pragma unroll
                        for (int ks = 0; ks < 4; ks++)
                            mma_f16_ss_cg2(tmem + nh * 256, ad + ks * 2, bd + ks * 2,
                                           IDESC, (uint32_t)((kc | ks) != 0));
                    }
                    TCGEN05_COMMIT_MC_CG2(sb + S_EMPTY + 8 * s, 0x3);
                }
                TCGEN05_COMMIT_MC_CG2(sb + S_DONE, 0x3);
            }
        }
    } else {
        // =================== EPILOGUE WARPS (0-3) ===================
        float zacc[4] = {0.f, 0.f, 0.f, 0.f};

        for (int t = 0; t < NTT; t++) {
            MBARRIER_WAIT_PARITY(sb + S_DONE, t & 1);
            TCGEN05_FENCE_AFTER();

            uint32_t bufA[32], bufB[32];
            TCGEN05_LD_32X32B_X32(bufA, tmem + 0);
            TCGEN05_WAIT_LD();
#pragma unroll
            for (int ch = 0; ch < 16; ch++) {
                if (ch < 15) {          // prefetch next chunk while consuming current
                    if (ch & 1) { TCGEN05_LD_32X32B_X32(bufA, tmem + (ch + 1) * 32); }
                    else        { TCGEN05_LD_32X32B_X32(bufB, tmem + (ch + 1) * 32); }
                }
                const uint32_t* cur = (ch & 1) ? bufB : bufA;
                const int nb = (t & 3) * TILE_N + ch * 32;
#pragma unroll
                for (int c = 0; c < 32; c++) {
                    float h = __uint_as_float(cur[c]) + s_b1[nb + c];
                    h = fmaxf(h, 0.f);
                    zacc[c & 3] = fmaf(h, s_w2[nb + c], zacc[c & 3]);
                }
                if (ch < 15) TCGEN05_WAIT_LD();
            }
            TCGEN05_FENCE_BEFORE();
            NAMED_BAR(2, 128);          // all 4 epilogue warps done reading D
            if (tid == 0) MBARRIER_ARRIVE_RANK0(sb + S_EDONE);

            if ((t & 3) == 3) {
                // ---- end of work item: emit z, reset, load next b1/W2 ----
                const int w  = t >> 2;
                const int wk = cid + N_CLUSTERS * w;
                const int e_w = wk >> 5;
                const int m0w = (wk & 31) * 256 + (int)rank * 128;
                const float z = (zacc[0] + zacc[1]) + (zacc[2] + zacc[3]);
                g_zbuf[(size_t)e_w * BATCH_SZ + m0w + tid] = z;
                zacc[0] = zacc[1] = zacc[2] = zacc[3] = 0.f;

                if (w + 1 < nwork) {
                    const int e_n = (cid + N_CLUSTERS * (w + 1)) >> 5;
                    for (int i = tid; i < HID; i += 128) {
                        s_b1[i] = __ldg(b1 + (size_t)e_n * HID + i);
                        s_w2[i] = __ldg(W2 + (size_t)e_n * HID + i);
                    }
                }
                NAMED_BAR(2, 128);      // reload visible before next epilogue
            }
        }
    }

    __syncthreads();
    if (wid == 0) {
        TCGEN05_RELINQUISH_CG2();
        TCGEN05_DEALLOC_CG2(tmem, 512);
    }
    CLUSTER_SYNC();   // peer MMAs/multicasts targeting our SMEM must be done
#endif  // TC_OK
}

// ---------------------------------------------------------------------------
// Host/device shared swizzle
// ---------------------------------------------------------------------------
__device__ __forceinline__ uint32_t swz128(uint32_t o) {
    return o ^ ((o >> 3) & 0x70);
}

// x fp32 [B][K] -> g_xa blobs: blob(mb, kc) 16KB, row r, cols kc*64..+63
__global__ void cvt_x_kernel(const float* __restrict__ x) {
    const int i = blockIdx.x * blockDim.x + threadIdx.x;   // < 8192*128
    const int m = i >> 7;
    const int g = i & 127;              // 16B group: kc = g>>3, within-chunk (g&7)
    const int kc = g >> 3;
    const float4 v0 = *(const float4*)(x + (size_t)m * IN_SZ + g * 8);
    const float4 v1 = *(const float4*)(x + (size_t)m * IN_SZ + g * 8 + 4);
    __nv_bfloat162 p0 = __floats2bfloat162_rn(v0.x, v0.y);
    __nv_bfloat162 p1 = __floats2bfloat162_rn(v0.z, v0.w);
    __nv_bfloat162 p2 = __floats2bfloat162_rn(v1.x, v1.y);
    __nv_bfloat162 p3 = __floats2bfloat162_rn(v1.z, v1.w);
    uint4 out;
    out.x = *(uint32_t*)&p0; out.y = *(uint32_t*)&p1;
    out.z = *(uint32_t*)&p2; out.w = *(uint32_t*)&p3;
    const int mb = m >> 7, r = m & 127;
    const uint32_t off = swz128((uint32_t)(r * 128 + (g & 7) * 16));
    *(uint4*)((char*)g_xa + (((size_t)(mb * 16 + kc)) << 14) + off) = out;
}

// W1 fp32 [E][K][H] -> g_wb blobs: blob(e, nt, rank, kc) 32KB,
// lr = nh*128+row, hid = nt*512+nh*256+rank*128+row, cols kc*64..+63
__global__ void cvt_w1_kernel(const float* __restrict__ W1) {
    __shared__ float tile[64][33];
    const int e  = blockIdx.z;
    const int kc = blockIdx.y;
    const int hb = blockIdx.x;          // hid block of 32
    const int t  = threadIdx.x;         // 0..255
    const float* src = W1 + ((size_t)e * IN_SZ + kc * 64) * HID + hb * 32;
#pragma unroll
    for (int it = 0; it < 8; it++) {
        const int lin = it * 256 + t;   // < 2048 = 64k x 32h
        const int kr = lin >> 5, hc = lin & 31;
        tile[kr][hc] = src[(size_t)kr * HID + hc];
    }
    __syncthreads();
    const int h = t >> 3, g = t & 7;    // h: 0..31, g: 16B group 0..7
    const int hid = hb * 32 + h;
    const int nt  = hid >> 9;
    const int nh  = (hid >> 8) & 1;
    const int rk  = (hid >> 7) & 1;
    const int row = hid & 127;
    const int lr  = nh * 128 + row;
    __nv_bfloat162 p0 = __floats2bfloat162_rn(tile[g * 8 + 0][h], tile[g * 8 + 1][h]);
    __nv_bfloat162 p1 = __floats2bfloat162_rn(tile[g * 8 + 2][h], tile[g * 8 + 3][h]);
    __nv_bfloat162 p2 = __floats2bfloat162_rn(tile[g * 8 + 4][h], tile[g * 8 + 5][h]);
    __nv_bfloat162 p3 = __floats2bfloat162_rn(tile[g * 8 + 6][h], tile[g * 8 + 7][h]);
    uint4 out;
    out.x = *(uint32_t*)&p0; out.y = *(uint32_t*)&p1;
    out.z = *(uint32_t*)&p2; out.w = *(uint32_t*)&p3;
    const size_t blob = (size_t)(((e * 4 + nt) * 2 + rk) * 16 + kc);
    const uint32_t off = swz128((uint32_t)(lr * 128 + g * 16));
    *(uint4*)((char*)g_wb + (blob << 15) + off) = out;
}

// ---------------------------------------------------------------------------
// Final reduce: out[m] = mean_e sigmoid(z[e][m] + b2[e])
// ---------------------------------------------------------------------------
__global__ void reduce_kernel(const float* __restrict__ b2, float* __restrict__ out) {
    const int i = blockIdx.x * blockDim.x + threadIdx.x;  // < 8192
    float s = 0.f;
#pragma unroll
    for (int ex = 0; ex < N_EXPERTS; ex++) {
        const float z = g_zbuf[(size_t)ex * BATCH_SZ + i] + b2[ex];
        s += 1.f / (1.f + __expf(-z));
    }
    out[i] = s * (1.f / N_EXPERTS);
}

// ---------------------------------------------------------------------------
// Harness entry
// ---------------------------------------------------------------------------
extern "C" void kernel_launch(void* const* d_in, const int* in_sizes, int n_in,
                              void* d_out, int out_size) {
    (void)in_sizes; (void)n_in; (void)out_size;
    const float* x  = (const float*)d_in[0];
    const float* W1 = (const float*)d_in[1];
    const float* b1 = (const float*)d_in[2];
    const float* W2 = (const float*)d_in[3];
    const float* b2 = (const float*)d_in[4];
    float* out = (float*)d_out;

    cudaFuncSetAttribute(gemm_fused, cudaFuncAttributeMaxDynamicSharedMemorySize,
                         (int)SMEM_BYTES);

    cvt_x_kernel<<<(BATCH_SZ * 128) / 256, 256>>>(x);

    dim3 tg(HID / 32, IN_SZ / 64, N_EXPERTS);   // (hb, kc, e)
    cvt_w1_kernel<<<tg, 256>>>(W1);

    // persistent: 148 CTAs = 74 cg2 clusters
    gemm_fused<<<2 * N_CLUSTERS, 192, SMEM_BYTES>>>(b1, W2);

    reduce_kernel<<<BATCH_SZ / 256, 256>>>(b2, out);
}

// round 12
// speedup vs baseline: 2.4089x; 1.5425x over previous
#include <cuda_runtime.h>
#include <cuda_bf16.h>
#include <cstdint>

// ---------------------------------------------------------------------------
// Arch gate: tcgen05 is sm_103a-ONLY (plain compute_103 phase must compile).
// ---------------------------------------------------------------------------
#if defined(__CUDA_ARCH__) && (__CUDA_ARCH__ == 1030) && defined(__CUDA_ARCH_FEAT_SM103_ALL)
#define TC_OK 1
#else
#define TC_OK 0
#endif

// ---------------------------------------------------------------------------
// Problem constants
// ---------------------------------------------------------------------------
#define N_EXPERTS 30
#define IN_SZ     1024
#define HID       2048
#define BATCH_SZ  8192

#define N_CLUSTERS 74            // 148 CTAs / 2
#define N_WORK     960           // 30 experts * 32 m-blocks of 256

// Exact power-of-2 operand scaling (folded out in epilogue)
#define X_SCALE   64.0f          // 2^6:  |x|max ~5.4 -> ~350 < 448
#define W_SCALE   8192.0f        // 2^13: |w|max 1/32 -> 256 < 448
#define INV_SCALE 1.9073486328125e-6f   // 2^-19 exact

// ---------------------------------------------------------------------------
// Device scratch (fp8 e4m3 blobs, SW128-swizzled SMEM images).
// g_xa: A blob(mb128, kc) = 16KB: x rows [mb*128,+128), k [kc*128,+128).
// g_wb: B blob(e, nt256, rank, kc) = 16KB: local row = n & 127 where
//       n = nt*256 + rank*128 + row;  k [kc*128,+128).
// ---------------------------------------------------------------------------
__device__ __align__(16) uint8_t g_xa[(size_t)BATCH_SZ * IN_SZ];                 // 8 MB
__device__ __align__(16) uint8_t g_wb[(size_t)N_EXPERTS * HID * IN_SZ];          // 63 MB
__device__ float g_zbuf[(size_t)N_EXPERTS * BATCH_SZ];                            // 1 MB

// ---------------------------------------------------------------------------
// PTX helpers
// ---------------------------------------------------------------------------
__device__ __forceinline__ uint32_t smem_to_u32(const void* p) {
    uint32_t a;
    asm("{ .reg .u64 t; cvta.to.shared.u64 t, %1; cvt.u32.u64 %0, t; }"
        : "=r"(a) : "l"(p));
    return a;
}

__device__ __forceinline__ uint32_t elect_one_pred() {
    uint32_t pred;
    asm volatile(
        "{\n\t.reg .pred p;\n\telect.sync _|p, 0xFFFFFFFF;\n\tselp.b32 %0, 1, 0, p;\n\t}"
        : "=r"(pred));
    return pred;
}

__device__ __forceinline__ uint32_t cluster_rank() {
    uint32_t r;
    asm("mov.u32 %0, %%cluster_ctarank;" : "=r"(r));
    return r;
}

#define MBARRIER_INIT(addr, cnt) \
    asm volatile("mbarrier.init.shared.b64 [%0], %1;" :: "r"((uint32_t)(addr)), "r"((uint32_t)(cnt)) : "memory")

#define MBARRIER_EXPECT_TX(addr, bytes) \
    asm volatile("mbarrier.arrive.expect_tx.shared.b64 _, [%0], %1;" \
        :: "r"((uint32_t)(addr)), "r"((uint32_t)(bytes)) : "memory")

// local wait, acquire at cta scope
#define MBARRIER_WAIT_PARITY(mbar_smem_addr, phase_parity) do { \
    uint32_t _mbar = (uint32_t)(mbar_smem_addr); \
    uint32_t _parity = (uint32_t)(phase_parity); \
    uint32_t _done; \
    asm volatile( \
        "{\n\t.reg .pred p;\n\t" \
        "mbarrier.try_wait.parity.acquire.cta.shared::cta.b64 p, [%1], %2;\n\t" \
        "selp.b32 %0, 1, 0, p;\n\t}" \
        : "=r"(_done) : "r"(_mbar), "r"(_parity) : "memory"); \
    if (!_done) { \
        asm volatile( \
            "{\n\t.reg .pred P1;\n\t" \
            "WAIT_LOOP_%=:\n\t" \
            "mbarrier.try_wait.parity.acquire.cta.shared::cta.b64 P1, [%0], %1, 0x989680;\n\t" \
            "@P1 bra.uni WAIT_DONE_%=;\n\t" \
            "bra.uni WAIT_LOOP_%=;\n\t" \
            "WAIT_DONE_%=:\n\t}" \
            :: "r"(_mbar), "r"(_parity) : "memory"); \
    } \
} while (0)

// cluster-scope acquire wait (peer-signaled barriers / peer data)
#define MBARRIER_WAIT_PARITY_CLU(mbar_smem_addr, phase_parity) do { \
    uint32_t _mbar = (uint32_t)(mbar_smem_addr); \
    uint32_t _parity = (uint32_t)(phase_parity); \
    uint32_t _done; \
    asm volatile( \
        "{\n\t.reg .pred p;\n\t" \
        "mbarrier.try_wait.parity.acquire.cluster.shared::cta.b64 p, [%1], %2;\n\t" \
        "selp.b32 %0, 1, 0, p;\n\t}" \
        : "=r"(_done) : "r"(_mbar), "r"(_parity) : "memory"); \
    if (!_done) { \
        asm volatile( \
            "{\n\t.reg .pred P1;\n\t" \
            "WAIT_LOOP_%=:\n\t" \
            "mbarrier.try_wait.parity.acquire.cluster.shared::cta.b64 P1, [%0], %1, 0x989680;\n\t" \
            "@P1 bra.uni WAIT_DONE_%=;\n\t" \
            "bra.uni WAIT_LOOP_%=;\n\t" \
            "WAIT_DONE_%=:\n\t}" \
            :: "r"(_mbar), "r"(_parity) : "memory"); \
    } \
} while (0)

// arrive on the same-offset mbarrier in cluster rank 0
#define MBARRIER_ARRIVE_RANK0(local_mbar_addr) \
    asm volatile( \
        "{\n\t.reg .b32 remAddr32;\n\t" \
        "mapa.shared::cluster.u32 remAddr32, %0, 0;\n\t" \
        "mbarrier.arrive.shared::cluster.b64 _, [remAddr32];\n\t}" \
        :: "r"((uint32_t)(local_mbar_addr)) : "memory")

#define CLUSTER_SYNC() do { \
    asm volatile("barrier.cluster.arrive.aligned;" ::: "memory"); \
    asm volatile("barrier.cluster.wait.aligned;" ::: "memory"); \
} while (0)

#define NAMED_BAR(id, cnt) \
    asm volatile("bar.sync %0, %1;" :: "r"(id), "r"(cnt) : "memory")

// bulk async copy global -> own-CTA shared, completion on LOCAL mbarrier
#define CP_BULK_G2S(dst_smem, src_gmem, bytes, mbar) \
    asm volatile("cp.async.bulk.shared::cluster.global.mbarrier::complete_tx::bytes " \
                 "[%0], [%1], %2, [%3];" \
        :: "r"((uint32_t)(dst_smem)), "l"(src_gmem), "r"((uint32_t)(bytes)), \
           "r"((uint32_t)(mbar)) : "memory")

// pack two floats to e4m3x2 (lo = first arg, hi = second; sm_89+)
__device__ __forceinline__ uint16_t f2e4m3x2(float lo, float hi) {
    uint16_t r;
    asm("cvt.rn.satfinite.e4m3x2.f32 %0, %1, %2;" : "=h"(r) : "f"(hi), "f"(lo));
    return r;
}

#if TC_OK
#define TCGEN05_ALLOC_CG2(smem_result_addr, nCols) \
    asm volatile("tcgen05.alloc.cta_group::2.sync.aligned.shared::cta.b32 [%0], %1;" \
        :: "r"((uint32_t)(smem_result_addr)), "r"((uint32_t)(nCols)) : "memory")

#define TCGEN05_DEALLOC_CG2(tmem_addr, nCols) \
    asm volatile("tcgen05.dealloc.cta_group::2.sync.aligned.b32 %0, %1;" \
        :: "r"(tmem_addr), "r"((uint32_t)(nCols)))

#define TCGEN05_RELINQUISH_CG2() \
    asm volatile("tcgen05.relinquish_alloc_permit.cta_group::2.sync.aligned;")

#define TCGEN05_COMMIT_MC_CG2(mbar_smem_addr, cta_mask) \
    asm volatile("tcgen05.commit.cta_group::2.mbarrier::arrive::one.shared::cluster.multicast::cluster.b64 [%0], %1;" \
        :: "r"((uint32_t)(mbar_smem_addr)), "h"((uint16_t)(cta_mask)) : "memory")

#define TCGEN05_WAIT_LD()  asm volatile("tcgen05.wait::ld.sync.aligned;" ::: "memory")
#define TCGEN05_WAIT_ST()  asm volatile("tcgen05.wait::st.sync.aligned;" ::: "memory")
#define TCGEN05_FENCE_BEFORE() asm volatile("tcgen05.fence::before_thread_sync;" ::: "memory")
#define TCGEN05_FENCE_AFTER()  asm volatile("tcgen05.fence::after_thread_sync;" ::: "memory")

#define TCGEN05_ST_32X32B_X1(tmem_addr, r0) \
    asm volatile("tcgen05.st.sync.aligned.32x32b.x1.b32 [%0], {%1};" \
        :: "r"(tmem_addr), "r"(r0) : "memory")

#define TCGEN05_LD_32X32B_X32(r, tmem_addr) \
    asm volatile( \
        "tcgen05.ld.sync.aligned.32x32b.x32.b32 " \
        "{%0, %1, %2, %3, %4, %5, %6, %7, " \
        " %8, %9, %10, %11, %12, %13, %14, %15, " \
        " %16, %17, %18, %19, %20, %21, %22, %23, " \
        " %24, %25, %26, %27, %28, %29, %30, %31}, [%32];" \
        : "=r"((r)[0]),  "=r"((r)[1]),  "=r"((r)[2]),  "=r"((r)[3]), \
          "=r"((r)[4]),  "=r"((r)[5]),  "=r"((r)[6]),  "=r"((r)[7]), \
          "=r"((r)[8]),  "=r"((r)[9]),  "=r"((r)[10]), "=r"((r)[11]), \
          "=r"((r)[12]), "=r"((r)[13]), "=r"((r)[14]), "=r"((r)[15]), \
          "=r"((r)[16]), "=r"((r)[17]), "=r"((r)[18]), "=r"((r)[19]), \
          "=r"((r)[20]), "=r"((r)[21]), "=r"((r)[22]), "=r"((r)[23]), \
          "=r"((r)[24]), "=r"((r)[25]), "=r"((r)[26]), "=r"((r)[27]), \
          "=r"((r)[28]), "=r"((r)[29]), "=r"((r)[30]), "=r"((r)[31]) \
        : "r"(tmem_addr))

// SW128 K-major SMEM descriptor (layout=SW128, Blackwell version=1, LBO=1, SBO=64)
static constexpr uint64_t SMEM_DESC_BASE_SW128 =
    (uint64_t(2) << 61) | (uint64_t(1) << 46) | (uint64_t(64) << 32) | (uint64_t(1) << 16);
#define MAKE_SMEM_DESC(base_addr) \
    (SMEM_DESC_BASE_SW128 | ((uint64_t)((base_addr) >> 4) & 0x3FFF))

// idesc for cta_group::2 kind::mxf8f6f4: M=256 (2<<27), UE8M0 (1<<23), N=256.
// sfa_id at [29:30], sfb_id at [4:5] select the K-step scale byte (all 127 here).
static constexpr uint32_t MXF8_IDESC_BASE =
    (2u << 27) | (1u << 23) | ((256u / 8) << 17);
__device__ __forceinline__ uint32_t mxf8_idesc(int k) {
    return MXF8_IDESC_BASE | ((uint32_t)k << 29) | ((uint32_t)k << 4);
}

// cg2 block-scaled MXFP8 SS MMA (proven in test_2cta_mma_mxf8.cu)
__device__ __forceinline__ void mma_mxf8_ss_cg2(uint32_t d, uint64_t ad, uint64_t bd,
                                                uint32_t idesc, uint32_t sca,
                                                uint32_t scb, uint32_t acc) {
    asm volatile(
        "{\n\t.reg .pred p;\n\tsetp.ne.u32 p, %6, 0;\n\t"
        "tcgen05.mma.cta_group::2.kind::mxf8f6f4.block_scale.scale_vec::1X "
        "[%0], %1, %2, %3, [%4], [%5], p;\n\t}"
        :: "r"(d), "l"(ad), "l"(bd), "r"(idesc), "r"(sca), "r"(scb), "r"(acc)
        : "memory");
}
#endif  // TC_OK

// ---------------------------------------------------------------------------
// Persistent cg2 FP8 GEMM. Tile = 256 rows x 256 cols; K-chunk = 128 (fp8).
// 64 chunks per work item (8 N-tiles x 8 K-chunks) -> ALL parity formulas
// identical to the passing R11 kernel. 192 threads:
//   w0-3 epilogue, w4 producer lane (bulk+relay), w5 MMA-issue lane (rank0).
// TMEM: D fp32 256 cols @0; unit scales SCA @256(4), SCB @260(8).
// ---------------------------------------------------------------------------
static constexpr int TILE_N   = 256;
static constexpr int STAGES   = 4;

static constexpr uint32_t S_TMEM  = 0;
static constexpr uint32_t S_FULLL = 16;                  // 4 x 8B per CTA (local tx)
static constexpr uint32_t S_FULLC = 48;                  // 4 x 8B rank0 (cnt=2 relays)
static constexpr uint32_t S_EMPTY = 80;                  // 4 x 8B per CTA (cnt=1)
static constexpr uint32_t S_DONE  = 112;                 // per CTA (commit-mc)
static constexpr uint32_t S_EDONE = 120;                 // rank0, cnt=2
static constexpr uint32_t S_B1    = 1024;
static constexpr uint32_t S_W2    = 1024 + 4 * HID;          // 9216
static constexpr uint32_t S_A     = S_W2 + 4 * HID;          // 17408 (1024-aligned)
static constexpr uint32_t A_STAGE_BYTES = 16384;             // 128 rows x 128 B
static constexpr uint32_t S_B     = S_A + STAGES * A_STAGE_BYTES;  // 82944
static constexpr uint32_t B_STAGE_BYTES = 16384;             // 128 n-rows x 128 B
static constexpr uint32_t SMEM_BYTES = S_B + STAGES * B_STAGE_BYTES; // 148480
static constexpr uint32_t TXL_BYTES = A_STAGE_BYTES + B_STAGE_BYTES; // 32768

__global__ void __launch_bounds__(192, 1) __cluster_dims__(2, 1, 1)
gemm_fused(const float* __restrict__ b1, const float* __restrict__ W2) {
#if TC_OK
    extern __shared__ __align__(1024) uint8_t smem[];
    const uint32_t sb = smem_to_u32(smem);
    const int tid  = threadIdx.x;
    const int wid  = tid >> 5;
    const uint32_t rank = cluster_rank();
    const int cid  = blockIdx.x >> 1;              // cluster id 0..73

    const int nwork = (N_WORK - cid + N_CLUSTERS - 1) / N_CLUSTERS;  // 13 or 12
    const int KKT   = nwork * 64;                  // total chunks, flat
    const int NTT   = nwork * 8;                   // total 256-col tiles, flat

    if (wid == 0) TCGEN05_ALLOC_CG2(sb + S_TMEM, 512);
    if (tid == 0) {
        if (rank == 0) {
            for (int s = 0; s < STAGES; s++) MBARRIER_INIT(sb + S_FULLC + 8 * s, 2);
            MBARRIER_INIT(sb + S_EDONE, 2);
        }
        for (int s = 0; s < STAGES; s++) {
            MBARRIER_INIT(sb + S_FULLL + 8 * s, 1);   // expect_tx arms each phase
            MBARRIER_INIT(sb + S_EMPTY + 8 * s, 1);
        }
        MBARRIER_INIT(sb + S_DONE, 1);
    }
    __syncthreads();

    uint32_t tmem;
    asm volatile("ld.shared.b32 %0, [%1];" : "=r"(tmem) : "r"(sb + S_TMEM));

    float* s_b1 = (float*)(smem + S_B1);
    float* s_w2 = (float*)(smem + S_W2);
    if (tid < 128) {
        const int e0 = cid >> 5;
        for (int i = tid; i < HID; i += 128) {
            s_b1[i] = __ldg(b1 + (size_t)e0 * HID + i);
            s_w2[i] = __ldg(W2 + (size_t)e0 * HID + i);
        }
        // unit ue8m0 scales (127 = 2^0) for SCA (4 cols) + SCB (8 cols),
        // written by all 4 warps -> replicated across TMEM subpartitions.
        const uint32_t wo = (uint32_t)(tid >> 5) << 21;
#pragma unroll
        for (int c = 0; c < 12; c++)
            TCGEN05_ST_32X32B_X1(tmem + 256 + c + wo, 0x7F7F7F7Fu);
        TCGEN05_WAIT_ST();
        TCGEN05_FENCE_BEFORE();
    }
    __syncthreads();
    CLUSTER_SYNC();   // barriers + scales ready cluster-wide before any arrival/tx

    if (wid == 4) {
        // =================== PRODUCER LANE (both CTAs) ===================
        if (elect_one_pred()) {
            const char* xa = (const char*)g_xa;
            const char* wb = (const char*)g_wb;

            for (int la = 0; la < KKT; la++) {
                const int s = la & 3;
                const int u = la >> 2;
                if (u >= 1)
                    MBARRIER_WAIT_PARITY(sb + S_EMPTY + 8 * s, (u - 1) & 1);

                const int wk = cid + N_CLUSTERS * (la >> 6);
                const int kc = la & 7;             // K-chunk of 128
                const int nt = (la >> 3) & 7;      // N-tile of 256
                const int e_la = wk >> 5;
                const int mb   = (wk & 31) * 2 + (int)rank;   // m-block of 128

                MBARRIER_EXPECT_TX(sb + S_FULLL + 8 * s, TXL_BYTES);
                const size_t aoff = ((size_t)(mb * 8 + kc)) << 14;
                CP_BULK_G2S(sb + S_A + (uint32_t)s * A_STAGE_BYTES,
                            xa + aoff, A_STAGE_BYTES, sb + S_FULLL + 8 * s);
                const size_t boff =
                    ((size_t)(e_la * 128 + nt * 16 + (int)rank * 8 + kc)) << 14;
                CP_BULK_G2S(sb + S_B + (uint32_t)s * B_STAGE_BYTES,
                            wb + boff, B_STAGE_BYTES, sb + S_FULLL + 8 * s);

                // relay previous chunk's completion to rank0's combined barrier
                if (la >= 1) {
                    const int p = la - 1;
                    MBARRIER_WAIT_PARITY(sb + S_FULLL + 8 * (p & 3), (p >> 2) & 1);
                    MBARRIER_ARRIVE_RANK0(sb + S_FULLC + 8 * (p & 3));
                }
            }
            const int p = KKT - 1;
            MBARRIER_WAIT_PARITY(sb + S_FULLL + 8 * (p & 3), (p >> 2) & 1);
            MBARRIER_ARRIVE_RANK0(sb + S_FULLC + 8 * (p & 3));
        }
    } else if (wid == 5) {
        // =================== MMA ISSUE LANE (rank 0 only) ===================
        if (rank == 0 && elect_one_pred()) {
            for (int t = 0; t < NTT; t++) {
                if (t >= 1)
                    MBARRIER_WAIT_PARITY_CLU(sb + S_EDONE, (t - 1) & 1);
                for (int kc = 0; kc < 8; kc++) {
                    const int kk = t * 8 + kc;
                    const int s  = kk & 3;
                    MBARRIER_WAIT_PARITY_CLU(sb + S_FULLC + 8 * s, (kk >> 2) & 1);
                    TCGEN05_FENCE_AFTER();
                    const uint64_t ad = MAKE_SMEM_DESC(sb + S_A + (uint32_t)s * A_STAGE_BYTES);
                    const uint64_t bd = MAKE_SMEM_DESC(sb + S_B + (uint32_t)s * B_STAGE_BYTES);
#pragma unroll
                    for (int ks = 0; ks < 4; ks++)     // 4 x K32 per 128-chunk
                        mma_mxf8_ss_cg2(tmem, ad + ks * 2, bd + ks * 2,
                                        mxf8_idesc(ks),
                                        tmem + 256, tmem + 260,
                                        (uint32_t)((kc | ks) != 0));
                    TCGEN05_COMMIT_MC_CG2(sb + S_EMPTY + 8 * s, 0x3);
                }
                TCGEN05_COMMIT_MC_CG2(sb + S_DONE, 0x3);
            }
        }
    } else {
        // =================== EPILOGUE WARPS (0-3) ===================
        float zacc[4] = {0.f, 0.f, 0.f, 0.f};

        for (int t = 0; t < NTT; t++) {
            MBARRIER_WAIT_PARITY(sb + S_DONE, t & 1);
            TCGEN05_FENCE_AFTER();

            uint32_t bufA[32], bufB[32];
            TCGEN05_LD_32X32B_X32(bufA, tmem + 0);
            TCGEN05_WAIT_LD();
#pragma unroll
            for (int ch = 0; ch < 8; ch++) {
                if (ch < 7) {          // prefetch next chunk while consuming current
                    if (ch & 1) { TCGEN05_LD_32X32B_X32(bufA, tmem + (ch + 1) * 32); }
                    else        { TCGEN05_LD_32X32B_X32(bufB, tmem + (ch + 1) * 32); }
                }
                const uint32_t* cur = (ch & 1) ? bufB : bufA;
                const int nb = (t & 7) * TILE_N + ch * 32;
#pragma unroll
                for (int c = 0; c < 32; c++) {
                    float h = fmaf(__uint_as_float(cur[c]), INV_SCALE, s_b1[nb + c]);
                    h = fmaxf(h, 0.f);
                    zacc[c & 3] = fmaf(h, s_w2[nb + c], zacc[c & 3]);
                }
                if (ch < 7) TCGEN05_WAIT_LD();
            }
            TCGEN05_FENCE_BEFORE();
            NAMED_BAR(2, 128);          // all 4 epilogue warps done reading D
            if (tid == 0) MBARRIER_ARRIVE_RANK0(sb + S_EDONE);

            if ((t & 7) == 7) {
                // ---- end of work item: emit z, reset, load next b1/W2 ----
                const int w  = t >> 3;
                const int wk = cid + N_CLUSTERS * w;
                const int e_w = wk >> 5;
                const int m0w = (wk & 31) * 256 + (int)rank * 128;
                const float z = (zacc[0] + zacc[1]) + (zacc[2] + zacc[3]);
                g_zbuf[(size_t)e_w * BATCH_SZ + m0w + tid] = z;
                zacc[0] = zacc[1] = zacc[2] = zacc[3] = 0.f;

                if (w + 1 < nwork) {
                    const int e_n = (cid + N_CLUSTERS * (w + 1)) >> 5;
                    for (int i = tid; i < HID; i += 128) {
                        s_b1[i] = __ldg(b1 + (size_t)e_n * HID + i);
                        s_w2[i] = __ldg(W2 + (size_t)e_n * HID + i);
                    }
                }
                NAMED_BAR(2, 128);      // reload visible before next epilogue
            }
        }
    }

    __syncthreads();
    if (wid == 0) {
        TCGEN05_RELINQUISH_CG2();
        TCGEN05_DEALLOC_CG2(tmem, 512);
    }
    CLUSTER_SYNC();   // peer MMAs/multicasts targeting our SMEM must be done
#endif  // TC_OK
}

// ---------------------------------------------------------------------------
// Host/device shared swizzle
// ---------------------------------------------------------------------------
__device__ __forceinline__ uint32_t swz128(uint32_t o) {
    return o ^ ((o >> 3) & 0x70);
}

// x fp32 [B][K] -> g_xa fp8 blobs (scaled by 2^6).
// Thread handles 16 consecutive k (16 B).
__global__ void cvt_x_kernel(const float* __restrict__ x) {
    const int i = blockIdx.x * blockDim.x + threadIdx.x;   // < 8192*64
    const int m = i >> 6;
    const int g = i & 63;               // 16B group; kc = g>>3
    const float* src = x + (size_t)m * IN_SZ + g * 16;
    float v[16];
#pragma unroll
    for (int j = 0; j < 16; j++) v[j] = src[j] * X_SCALE;
    uint32_t w[4];
#pragma unroll
    for (int q = 0; q < 4; q++) {
        const uint16_t p01 = f2e4m3x2(v[4 * q + 0], v[4 * q + 1]);
        const uint16_t p23 = f2e4m3x2(v[4 * q + 2], v[4 * q + 3]);
        w[q] = (uint32_t)p01 | ((uint32_t)p23 << 16);
    }
    uint4 out = make_uint4(w[0], w[1], w[2], w[3]);
    const int mb = m >> 7, r = m & 127, kc = g >> 3;
    const uint32_t off = swz128((uint32_t)(r * 128 + (g & 7) * 16));
    *(uint4*)((char*)g_xa + (((size_t)(mb * 8 + kc)) << 14) + off) = out;
}

// W1 fp32 [E][K][H] -> g_wb fp8 blobs (scaled by 2^13), transposed to K-major.
// Block: (hb 32 hid) x (kc 128 k). 256 threads.
__global__ void cvt_w1_kernel(const float* __restrict__ W1) {
    __shared__ float tile[128][33];
    const int e  = blockIdx.z;
    const int kc = blockIdx.y;          // K-chunk of 128
    const int hb = blockIdx.x;          // hid block of 32
    const int t  = threadIdx.x;         // 0..255
    const float* src = W1 + ((size_t)e * IN_SZ + kc * 128) * HID + hb * 32;
#pragma unroll
    for (int it = 0; it < 16; it++) {
        const int lin = it * 256 + t;   // < 4096 = 128k x 32h
        const int kr = lin >> 5, hc = lin & 31;
        tile[kr][hc] = src[(size_t)kr * HID + hc];
    }
    __syncthreads();
    const int h = t >> 3, g = t & 7;    // h: 0..31, g: 16B group 0..7
    float v[16];
#pragma unroll
    for (int j = 0; j < 16; j++) v[j] = tile[g * 16 + j][h] * W_SCALE;
    uint32_t w[4];
#pragma unroll
    for (int q = 0; q < 4; q++) {
        const uint16_t p01 = f2e4m3x2(v[4 * q + 0], v[4 * q + 1]);
        const uint16_t p23 = f2e4m3x2(v[4 * q + 2], v[4 * q + 3]);
        w[q] = (uint32_t)p01 | ((uint32_t)p23 << 16);
    }
    uint4 out = make_uint4(w[0], w[1], w[2], w[3]);
    const int hid = hb * 32 + h;
    const int nt  = hid >> 8;
    const int rk  = (hid >> 7) & 1;
    const int row = hid & 127;
    const size_t blob = (size_t)(e * 128 + nt * 16 + rk * 8 + kc);
    const uint32_t off = swz128((uint32_t)(row * 128 + g * 16));
    *(uint4*)((char*)g_wb + (blob << 14) + off) = out;
}

// ---------------------------------------------------------------------------
// Final reduce: out[m] = mean_e sigmoid(z[e][m] + b2[e]); 4 threads/output
// ---------------------------------------------------------------------------
__global__ void reduce_kernel(const float* __restrict__ b2, float* __restrict__ out) {
    const int tid = blockIdx.x * blockDim.x + threadIdx.x;  // < 32768
    const int i = tid >> 2, l = tid & 3;
    float s = 0.f;
#pragma unroll
    for (int ex = l; ex < N_EXPERTS; ex += 4) {
        const float z = g_zbuf[(size_t)ex * BATCH_SZ + i] + b2[ex];
        s += 1.f / (1.f + __expf(-z));
    }
    s += __shfl_xor_sync(0xFFFFFFFFu, s, 1);
    s += __shfl_xor_sync(0xFFFFFFFFu, s, 2);
    if (l == 0) out[i] = s * (1.f / N_EXPERTS);
}

// ---------------------------------------------------------------------------
// Harness entry
// ---------------------------------------------------------------------------
extern "C" void kernel_launch(void* const* d_in, const int* in_sizes, int n_in,
                              void* d_out, int out_size) {
    (void)in_sizes; (void)n_in; (void)out_size;
    const float* x  = (const float*)d_in[0];
    const float* W1 = (const float*)d_in[1];
    const float* b1 = (const float*)d_in[2];
    const float* W2 = (const float*)d_in[3];
    const float* b2 = (const float*)d_in[4];
    float* out = (float*)d_out;

    cudaFuncSetAttribute(gemm_fused, cudaFuncAttributeMaxDynamicSharedMemorySize,
                         (int)SMEM_BYTES);

    cvt_x_kernel<<<(BATCH_SZ * 64) / 256, 256>>>(x);

    dim3 tg(HID / 32, IN_SZ / 128, N_EXPERTS);   // (hb, kc, e)
    cvt_w1_kernel<<<tg, 256>>>(W1);

    // persistent: 148 CTAs = 74 cg2 clusters
    gemm_fused<<<2 * N_CLUSTERS, 192, SMEM_BYTES>>>(b1, W2);

    reduce_kernel<<<(BATCH_SZ * 4) / 256, 256>>>(b2, out);
}